// round 13
// baseline (speedup 1.0000x reference)
#include <cuda_runtime.h>
#include <cuda_bf16.h>
#include <cstddef>
#include <cstdint>

// ---------------------------------------------------------------------------
// Problem constants
// ---------------------------------------------------------------------------
#define NROWS   100352            // 32 * 56 * 56 tokens
#define NWIN    2048              // 32 * 64 windows
#define SCALE_Q 0.17677669529663689f   // 32^-0.5

// ---------------------------------------------------------------------------
// Scratch (static __device__ arrays; allocation is forbidden)
// ---------------------------------------------------------------------------
__device__ __align__(16) __nv_bfloat16 g_ywin[100352 * 256];   // LN1 out (win order)
__device__ __align__(16) __nv_bfloat16 g_qkv [100352 * 768];   // qkv, bf16
__device__ __align__(16) __nv_bfloat16 g_attn[100352 * 256];   // attention out
__device__ float                       g_x1  [100352 * 256];   // shortcut + proj
__device__ __align__(16) __nv_bfloat16 g_h2  [100352 * 256];   // LN2 out
__device__ __align__(16) __nv_bfloat16 g_act [100352 * 1024];  // gelu(mlp1)
__device__ __align__(16) __nv_bfloat16 g_wbf [786432];         // all 4 weights, bf16

#define WOFF_QKV  0
#define WOFF_PROJ 196608
#define WOFF_W1   262144
#define WOFF_W2   524288

// ---------------------------------------------------------------------------
// window-order row <-> x-order row mapping (shift = 3, 8x8 windows of 7x7)
// ---------------------------------------------------------------------------
__device__ __forceinline__ int win_to_x_row(int m) {
    int w  = m / 49;
    int t  = m - w * 49;
    int b  = w >> 6;
    int wi = w & 63;
    int tr = t / 7;
    int tc = t - tr * 7;
    int gr = ((wi >> 3) * 7) + tr;
    int gc = ((wi & 7) * 7) + tc;
    int r = gr + 3; if (r >= 56) r -= 56;
    int c = gc + 3; if (c >= 56) c -= 56;
    return b * 3136 + r * 56 + c;
}

__device__ __forceinline__ float gelu_tanh(float x) {
    float x3 = x * x * x;
    return 0.5f * x * (1.0f + tanhf(0.7978845608028654f * (x + 0.044715f * x3)));
}

__device__ __forceinline__ uint2 pack4_bf16(float4 v) {
    __nv_bfloat162 lo = __floats2bfloat162_rn(v.x, v.y);
    __nv_bfloat162 hi = __floats2bfloat162_rn(v.z, v.w);
    uint2 r;
    r.x = *(uint32_t*)&lo;
    r.y = *(uint32_t*)&hi;
    return r;
}

__device__ __forceinline__ uint32_t pack2_bf16(float a, float b) {
    __nv_bfloat162 t = __floats2bfloat162_rn(a, b);
    return *(uint32_t*)&t;
}

// ---------------------------------------------------------------------------
// PTX helpers
// ---------------------------------------------------------------------------
__device__ __forceinline__ void ldsm4(uint32_t r[4], const void* p) {
    uint32_t a = (uint32_t)__cvta_generic_to_shared(p);
    asm("ldmatrix.sync.aligned.m8n8.x4.shared.b16 {%0,%1,%2,%3}, [%4];"
        : "=r"(r[0]), "=r"(r[1]), "=r"(r[2]), "=r"(r[3]) : "r"(a) : "memory");
}
__device__ __forceinline__ void ldsm4t(uint32_t r[4], const void* p) {
    uint32_t a = (uint32_t)__cvta_generic_to_shared(p);
    asm("ldmatrix.sync.aligned.m8n8.x4.trans.shared.b16 {%0,%1,%2,%3}, [%4];"
        : "=r"(r[0]), "=r"(r[1]), "=r"(r[2]), "=r"(r[3]) : "r"(a) : "memory");
}
__device__ __forceinline__ void mma_bf16(float c[4], const uint32_t a[4],
                                         uint32_t b0, uint32_t b1) {
    asm("mma.sync.aligned.m16n8k16.row.col.f32.bf16.bf16.f32 "
        "{%0,%1,%2,%3}, {%4,%5,%6,%7}, {%8,%9}, {%0,%1,%2,%3};"
        : "+f"(c[0]), "+f"(c[1]), "+f"(c[2]), "+f"(c[3])
        : "r"(a[0]), "r"(a[1]), "r"(a[2]), "r"(a[3]), "r"(b0), "r"(b1));
}
__device__ __forceinline__ void cpasync16(void* dst, const void* src) {
    uint32_t d = (uint32_t)__cvta_generic_to_shared(dst);
    asm volatile("cp.async.cg.shared.global [%0], [%1], 16;" :: "r"(d), "l"(src));
}
__device__ __forceinline__ void cp_commit() {
    asm volatile("cp.async.commit_group;");
}
template <int N>
__device__ __forceinline__ void cp_wait() {
    asm volatile("cp.async.wait_group %0;" :: "n"(N));
}

// ---------------------------------------------------------------------------
// Weight conversion: fp32 -> bf16, once per launch
// ---------------------------------------------------------------------------
__global__ void __launch_bounds__(1024) wconv_kernel(const float* __restrict__ qkv_w,
                                                     const float* __restrict__ proj_w,
                                                     const float* __restrict__ w1,
                                                     const float* __restrict__ w2,
                                                     __nv_bfloat16* __restrict__ dst) {
    int i = blockIdx.x * 1024 + threadIdx.x;   // grid = 768
    float v;
    if      (i < WOFF_PROJ) v = qkv_w[i];
    else if (i < WOFF_W1)   v = proj_w[i - WOFF_PROJ];
    else if (i < WOFF_W2)   v = w1[i - WOFF_W1];
    else                    v = w2[i - WOFF_W2];
    dst[i] = __float2bfloat16(v);
}

// ---------------------------------------------------------------------------
// LayerNorm (LN1 only): one warp per 256-wide row, gather + bf16 output.
// ---------------------------------------------------------------------------
__global__ void __launch_bounds__(256) ln_kernel(const float* __restrict__ in,
                                                 const float* __restrict__ gamma,
                                                 const float* __restrict__ beta,
                                                 __nv_bfloat16* __restrict__ out) {
    int gw   = (blockIdx.x * blockDim.x + threadIdx.x) >> 5;
    int lane = threadIdx.x & 31;
    if (gw >= NROWS) return;
    int src = win_to_x_row(gw);

    const float4* row = (const float4*)(in + (size_t)src * 256);
    float4 v0 = row[lane];
    float4 v1 = row[lane + 32];

    float s  = v0.x + v0.y + v0.z + v0.w + v1.x + v1.y + v1.z + v1.w;
    float ss = v0.x*v0.x + v0.y*v0.y + v0.z*v0.z + v0.w*v0.w
             + v1.x*v1.x + v1.y*v1.y + v1.z*v1.z + v1.w*v1.w;
#pragma unroll
    for (int o = 16; o; o >>= 1) {
        s  += __shfl_xor_sync(0xffffffffu, s,  o);
        ss += __shfl_xor_sync(0xffffffffu, ss, o);
    }
    float mu  = s * (1.0f / 256.0f);
    float inv = rsqrtf(ss * (1.0f / 256.0f) - mu * mu + 1e-5f);

    float4 g0 = ((const float4*)gamma)[lane];
    float4 g1 = ((const float4*)gamma)[lane + 32];
    float4 b0 = ((const float4*)beta)[lane];
    float4 b1 = ((const float4*)beta)[lane + 32];

    float4 o0, o1;
    o0.x = (v0.x - mu) * inv * g0.x + b0.x;
    o0.y = (v0.y - mu) * inv * g0.y + b0.y;
    o0.z = (v0.z - mu) * inv * g0.z + b0.z;
    o0.w = (v0.w - mu) * inv * g0.w + b0.w;
    o1.x = (v1.x - mu) * inv * g1.x + b1.x;
    o1.y = (v1.y - mu) * inv * g1.y + b1.y;
    o1.z = (v1.z - mu) * inv * g1.z + b1.z;
    o1.w = (v1.w - mu) * inv * g1.w + b1.w;

    uint2* orow = (uint2*)(out + (size_t)gw * 256);
    orow[lane]      = pack4_bf16(o0);
    orow[lane + 32] = pack4_bf16(o1);
}

// ---------------------------------------------------------------------------
// WIDE bf16 tensor-core GEMM: BM=128, BN=256, BK=32, 4-stage cp.async.
// 256 threads = 8 warps (2m x 4n), warp tile 64x64 (ldsm/mma = 0.25,
// 32 independent acc tiles for deep ILP). 1 block/SM (acc-heavy: ~180 regs).
// A smem [m][k] pitch 40 (proven conflict-free); B smem [k][n] pitch 264
// (proven in proj_ln). Exact tail waits.
// Dynamic smem: 4*(128*40 + 32*264)*2 = 108544 B.
// ---------------------------------------------------------------------------
#define EPI_BIAS 0
#define EPI_GELU 1
#define EPI_MLP2 3

#define W_AS 40
#define W_BS 264
#define W_A_STG (128 * W_AS)            // 5120 elems
#define W_B_STG (32 * W_BS)             // 8448 elems
#define WIDE_SMEM ((4 * W_A_STG + 4 * W_B_STG) * 2)   // 108544 bytes

template <int EPI, bool OUT_BF16>
__global__ void __launch_bounds__(256, 1) gemm_wide(const __nv_bfloat16* __restrict__ A,
                                                    const __nv_bfloat16* __restrict__ B,
                                                    const float* __restrict__ bias,
                                                    void* __restrict__ Cout,
                                                    const float* __restrict__ res,
                                                    int N, int K) {
    extern __shared__ __align__(16) __nv_bfloat16 smp[];
    __nv_bfloat16* Asm = smp;
    __nv_bfloat16* Bsm = smp + 4 * W_A_STG;

    const int tid  = threadIdx.x;
    const int lane = tid & 31;
    const int wid  = tid >> 5;
    const int bm   = blockIdx.x * 128;
    const int bn   = blockIdx.y * 256;
    const int wm   = (wid & 1) * 64;
    const int wn   = (wid >> 1) * 64;

    const __nv_bfloat16* Ab = A + (size_t)bm * K;
    const __nv_bfloat16* Bb = B + bn;

    float acc[4][8][4] = {};

    // one 32-wide K chunk: A 128x32 (2 x 16B/thread), B 32x256 (4 x 16B/thread)
    auto load_tile = [&](int k0, int stg) {
        __nv_bfloat16* as = Asm + stg * W_A_STG;
        __nv_bfloat16* bs = Bsm + stg * W_B_STG;
#pragma unroll
        for (int i = 0; i < 2; i++) {
            int c = tid + i * 256;              // 0..511
            int row = c >> 2, kc = (c & 3) * 8;
            cpasync16(&as[row * W_AS + kc], Ab + (size_t)row * K + k0 + kc);
        }
#pragma unroll
        for (int i = 0; i < 4; i++) {
            int c = tid + i * 256;              // 0..1023
            int k = c >> 5, n = (c & 31) * 8;
            cpasync16(&bs[k * W_BS + n], Bb + (size_t)(k0 + k) * N + n);
        }
        cp_commit();
    };

    const int nIter = K >> 5;                   // K/32
    load_tile(0, 0);
    load_tile(32, 1);
    load_tile(64, 2);

    for (int i = 0; i < nIter; i++) {
        if      (i + 2 < nIter) cp_wait<2>();
        else if (i + 1 < nIter) cp_wait<1>();
        else                    cp_wait<0>();
        __syncthreads();
        if (i + 3 < nIter) load_tile((i + 3) * 32, (i + 3) & 3);

        const __nv_bfloat16* as = Asm + (i & 3) * W_A_STG;
        const __nv_bfloat16* bs = Bsm + (i & 3) * W_B_STG;
#pragma unroll
        for (int ks = 0; ks < 32; ks += 16) {
            uint32_t af[4][4];
#pragma unroll
            for (int mi = 0; mi < 4; mi++)
                ldsm4(af[mi], as + (wm + mi * 16 + (lane & 15)) * W_AS
                                 + ks + (lane >> 4) * 8);
#pragma unroll
            for (int np = 0; np < 4; np++) {
                uint32_t bf[4];
                ldsm4t(bf, bs + (ks + (lane & 7) + ((lane >> 3) & 1) * 8) * W_BS
                              + wn + np * 16 + (lane >> 4) * 8);
#pragma unroll
                for (int mi = 0; mi < 4; mi++) {
                    mma_bf16(acc[mi][np * 2 + 0], af[mi], bf[0], bf[1]);
                    mma_bf16(acc[mi][np * 2 + 1], af[mi], bf[2], bf[3]);
                }
            }
        }
    }

    // ---------------- epilogue ----------------
    float bv0[8], bv1[8];
#pragma unroll
    for (int ni = 0; ni < 8; ni++) {
        int c = bn + wn + ni * 8 + 2 * (lane & 3);
        bv0[ni] = bias[c];
        bv1[ni] = bias[c + 1];
    }

#pragma unroll
    for (int mi = 0; mi < 4; mi++) {
#pragma unroll
        for (int half = 0; half < 2; half++) {
            int r = bm + wm + mi * 16 + (lane >> 2) + half * 8;
            size_t rowoff = (size_t)r * N;
#pragma unroll
            for (int ni = 0; ni < 8; ni++) {
                int c = bn + wn + ni * 8 + 2 * (lane & 3);
                float v0 = acc[mi][ni][half * 2 + 0] + bv0[ni];
                float v1 = acc[mi][ni][half * 2 + 1] + bv1[ni];
                if (EPI == EPI_GELU) { v0 = gelu_tanh(v0); v1 = gelu_tanh(v1); }
                if (EPI == EPI_MLP2) {
                    float2 rr = *(const float2*)(res + rowoff + c);
                    v0 += rr.x; v1 += rr.y;
                }
                if (OUT_BF16) {
                    __nv_bfloat162 w = __floats2bfloat162_rn(v0, v1);
                    *(__nv_bfloat162*)((__nv_bfloat16*)Cout + rowoff + c) = w;
                } else {
                    float2 w = {v0, v1};
                    *(float2*)((float*)Cout + rowoff + c) = w;
                }
            }
        }
    }
}

// ---------------------------------------------------------------------------
// PROJ + residual + LN2 fused GEMM (unchanged from R10/R11).
// ---------------------------------------------------------------------------
#define PS_AS 40
#define PS_BS 264
#define PS_A_STG (64 * PS_AS)
#define PS_B_STG (32 * PS_BS)
#define PROJ_SMEM ((4 * PS_A_STG + 4 * PS_B_STG) * 2)   // 88064

__global__ void __launch_bounds__(256, 2) gemm_proj_ln(
    const __nv_bfloat16* __restrict__ A,     // attn out (window order)
    const __nv_bfloat16* __restrict__ B,     // proj_w bf16 [k][n]
    const float* __restrict__ bias,
    const float* __restrict__ xres,          // original input x
    const float* __restrict__ gamma,         // norm2_g
    const float* __restrict__ beta,          // norm2_b
    float* __restrict__ x1,
    __nv_bfloat16* __restrict__ h2) {
    extern __shared__ __align__(16) __nv_bfloat16 smp[];
    __nv_bfloat16* Asm = smp;
    __nv_bfloat16* Bsm = smp + 4 * PS_A_STG;

    const int tid  = threadIdx.x;
    const int lane = tid & 31;
    const int wid  = tid >> 5;
    const int bm   = blockIdx.x * 64;
    const int wm   = (wid & 1) * 32;
    const int wn   = (wid >> 1) * 64;
    const int K = 256, N = 256;

    const __nv_bfloat16* Ab = A + (size_t)bm * K;

    float acc[2][8][4] = {};

    auto load_tile = [&](int k0, int stg) {
        __nv_bfloat16* as = Asm + stg * PS_A_STG;
        __nv_bfloat16* bs = Bsm + stg * PS_B_STG;
        {
            int row = tid >> 2, kc = (tid & 3) * 8;      // A: 64x32
            cpasync16(&as[row * PS_AS + kc], Ab + (size_t)row * K + k0 + kc);
        }
#pragma unroll
        for (int i = 0; i < 4; i++) {                    // B: 32x256
            int c = tid + i * 256;
            int k = c >> 5, n = (c & 31) * 8;
            cpasync16(&bs[k * PS_BS + n], B + (size_t)(k0 + k) * N + n);
        }
        cp_commit();
    };

    const int nIter = 8;                                 // K/32
    load_tile(0, 0);
    load_tile(32, 1);
    load_tile(64, 2);

    for (int i = 0; i < nIter; i++) {
        if      (i + 2 < nIter) cp_wait<2>();
        else if (i + 1 < nIter) cp_wait<1>();
        else                    cp_wait<0>();
        __syncthreads();
        if (i + 3 < nIter) load_tile((i + 3) * 32, (i + 3) & 3);

        const __nv_bfloat16* as = Asm + (i & 3) * PS_A_STG;
        const __nv_bfloat16* bs = Bsm + (i & 3) * PS_B_STG;
#pragma unroll
        for (int ks = 0; ks < 32; ks += 16) {
            uint32_t af[2][4];
#pragma unroll
            for (int mi = 0; mi < 2; mi++)
                ldsm4(af[mi], as + (wm + mi * 16 + (lane & 15)) * PS_AS
                                 + ks + (lane >> 4) * 8);
#pragma unroll
            for (int np = 0; np < 4; np++) {
                uint32_t bf[4];
                ldsm4t(bf, bs + (ks + (lane & 7) + ((lane >> 3) & 1) * 8) * PS_BS
                              + wn + np * 16 + (lane >> 4) * 8);
                mma_bf16(acc[0][np * 2 + 0], af[0], bf[0], bf[1]);
                mma_bf16(acc[1][np * 2 + 0], af[1], bf[0], bf[1]);
                mma_bf16(acc[0][np * 2 + 1], af[0], bf[2], bf[3]);
                mma_bf16(acc[1][np * 2 + 1], af[1], bf[2], bf[3]);
            }
        }
    }
    __syncthreads();   // all warps done with pipeline smem before x1 staging

    // ---------------- epilogue: x1 = acc + bias + x, staged in smem ----------
    float* x1s = (float*)smp;        // 64 rows x stride 264 fp32
    const int S = 264;

    float bv0[8], bv1[8];
#pragma unroll
    for (int ni = 0; ni < 8; ni++) {
        int c = wn + ni * 8 + 2 * (lane & 3);
        bv0[ni] = bias[c];
        bv1[ni] = bias[c + 1];
    }

#pragma unroll
    for (int mi = 0; mi < 2; mi++) {
#pragma unroll
        for (int half = 0; half < 2; half++) {
            int row  = wm + mi * 16 + (lane >> 2) + half * 8;   // 0..63
            int xrow = win_to_x_row(bm + row);
            size_t off = (size_t)xrow * 256;
#pragma unroll
            for (int ni = 0; ni < 8; ni++) {
                int c = wn + ni * 8 + 2 * (lane & 3);
                float v0 = acc[mi][ni][half * 2 + 0] + bv0[ni];
                float v1 = acc[mi][ni][half * 2 + 1] + bv1[ni];
                float2 rr = *(const float2*)(xres + off + c);
                v0 += rr.x; v1 += rr.y;
                float2 w = {v0, v1};
                *(float2*)(x1 + off + c)      = w;
                *(float2*)(&x1s[row * S + c]) = w;
            }
        }
    }
    __syncthreads();

    // ---------------- in-block LN2: 8 rows per warp -> h2 bf16 ---------------
    float4 g0 = *(const float4*)(gamma + lane * 8);
    float4 g1 = *(const float4*)(gamma + lane * 8 + 4);
    float4 be0 = *(const float4*)(beta + lane * 8);
    float4 be1 = *(const float4*)(beta + lane * 8 + 4);

#pragma unroll
    for (int rr = 0; rr < 8; rr++) {
        int row = wid * 8 + rr;
        float4 u0 = *(const float4*)(&x1s[row * S + lane * 8]);
        float4 u1 = *(const float4*)(&x1s[row * S + lane * 8 + 4]);

        float s  = u0.x + u0.y + u0.z + u0.w + u1.x + u1.y + u1.z + u1.w;
        float ss = u0.x*u0.x + u0.y*u0.y + u0.z*u0.z + u0.w*u0.w
                 + u1.x*u1.x + u1.y*u1.y + u1.z*u1.z + u1.w*u1.w;
#pragma unroll
        for (int o = 16; o; o >>= 1) {
            s  += __shfl_xor_sync(0xffffffffu, s,  o);
            ss += __shfl_xor_sync(0xffffffffu, ss, o);
        }
        float mu  = s * (1.0f / 256.0f);
        float inv = rsqrtf(ss * (1.0f / 256.0f) - mu * mu + 1e-5f);

        float4 o0, o1;
        o0.x = (u0.x - mu) * inv * g0.x + be0.x;
        o0.y = (u0.y - mu) * inv * g0.y + be0.y;
        o0.z = (u0.z - mu) * inv * g0.z + be0.z;
        o0.w = (u0.w - mu) * inv * g0.w + be0.w;
        o1.x = (u1.x - mu) * inv * g1.x + be1.x;
        o1.y = (u1.y - mu) * inv * g1.y + be1.y;
        o1.z = (u1.z - mu) * inv * g1.z + be1.z;
        o1.w = (u1.w - mu) * inv * g1.w + be1.w;

        int xrow = win_to_x_row(bm + row);
        uint2 p0 = pack4_bf16(o0);
        uint2 p1 = pack4_bf16(o1);
        uint4 pk = make_uint4(p0.x, p0.y, p1.x, p1.y);
        *(uint4*)(h2 + (size_t)xrow * 256 + lane * 8) = pk;
    }
}

// ---------------------------------------------------------------------------
// Tensor-core windowed attention (R11 occupancy-tuned version; unchanged).
// ---------------------------------------------------------------------------
#define ATS 40

__global__ void __launch_bounds__(64) attn_tc(const __nv_bfloat16* __restrict__ qkv,
                                              const float* __restrict__ bias_table,
                                              __nv_bfloat16* __restrict__ out) {
    __shared__ __align__(16) __nv_bfloat16 sK[2][64 * ATS];
    __shared__ __align__(16) __nv_bfloat16 sV[2][64 * ATS];
    __shared__ float sB[2][169];
    __shared__ int   sInfo[64];

    const int w     = blockIdx.x >> 2;
    const int wp    = threadIdx.x >> 5;
    const int lane  = threadIdx.x & 31;
    const int h     = (blockIdx.x & 3) * 2 + wp;
    const int wbase = w * 49;
    const int wi    = w & 63;

    if (threadIdx.x < 64) {
        int j = threadIdx.x;
        int info;
        if (j < 49) {
            int rj = j / 7, cj = j - (j / 7) * 7;
            int gr = (wi >> 3) * 7 + rj;
            int gc = (wi & 7) * 7 + cj;
            int rh = (gr < 49) ? 0 : ((gr < 53) ? 1 : 2);
            int rc = (gc < 49) ? 0 : ((gc < 53) ? 1 : 2);
            int key = rj + 13 * cj;
            info = key | ((rh * 3 + rc) << 8) | (1 << 16);
        } else {
            info = 0 | (255 << 8);
        }
        sInfo[j] = info;
    }

    for (int idx = lane; idx < 169; idx += 32) sB[wp][idx] = bias_table[idx * 8 + h];

    // K/V rows 0..48 from gmem (coalesced 16B chunks)
    for (int tsk = lane; tsk < 196; tsk += 32) {
        int row = tsk >> 2, seg = (tsk & 3) * 8;
        const __nv_bfloat16* base = qkv + (size_t)(wbase + row) * 768 + h * 32 + seg;
        int off = row * ATS + seg;
        *(uint4*)&sK[wp][off] = *(const uint4*)(base + 256);
        *(uint4*)&sV[wp][off] = *(const uint4*)(base + 512);
    }
    // zero pad rows 49..63
    for (int z = lane; z < 60; z += 32) {
        int row = 49 + (z >> 2), seg = (z & 3) * 8;
        int off = row * ATS + seg;
        uint4 zz = make_uint4(0, 0, 0, 0);
        *(uint4*)&sK[wp][off] = zz;
        *(uint4*)&sV[wp][off] = zz;
    }
    __syncthreads();

    const int q2 = 2 * (lane & 3);
    const int r = lane >> 2;
    const __nv_bfloat16* qb = qkv + (size_t)wbase * 768 + h * 32;   // row stride 768

#pragma unroll
    for (int mt = 0; mt < 4; mt++) {
        const int r0 = mt * 16 + r;
        const int r1 = r0 + 8;
        const bool v0 = (r0 < 49), v1 = (r1 < 49);
        uint32_t qf[2][4];
#pragma unroll
        for (int ks = 0; ks < 2; ks++) {
            const int cc = q2 + ks * 16;
            qf[ks][0] = v0 ? *(const uint32_t*)(qb + (size_t)r0 * 768 + cc)     : 0u;
            qf[ks][1] = v1 ? *(const uint32_t*)(qb + (size_t)r1 * 768 + cc)     : 0u;
            qf[ks][2] = v0 ? *(const uint32_t*)(qb + (size_t)r0 * 768 + cc + 8) : 0u;
            qf[ks][3] = v1 ? *(const uint32_t*)(qb + (size_t)r1 * 768 + cc + 8) : 0u;
        }

        float c[8][4] = {};
#pragma unroll
        for (int nt = 0; nt < 4; nt++) {
#pragma unroll
            for (int ks = 0; ks < 2; ks++) {
                uint32_t kf[4];
                ldsm4(kf, &sK[wp][(nt * 16 + (lane & 7) + ((lane >> 4) & 1) * 8) * ATS
                                  + ks * 16 + ((lane >> 3) & 1) * 8]);
                mma_bf16(c[2 * nt + 0], qf[ks], kf[0], kf[1]);
                mma_bf16(c[2 * nt + 1], qf[ks], kf[2], kf[3]);
            }
        }

        int infLo = sInfo[r0 < 64 ? r0 : 0], infHi = sInfo[r1 < 64 ? r1 : 0];
        int keyLo = (infLo & 255) + 84, regLo = (infLo >> 8) & 255;
        int keyHi = (infHi & 255) + 84, regHi = (infHi >> 8) & 255;

        float sumLo = 0.0f, sumHi = 0.0f;
#pragma unroll
        for (int u = 0; u < 8; u++) {
#pragma unroll
            for (int e = 0; e < 2; e++) {
                int inf = sInfo[u * 8 + q2 + e];
                float pLo, pHi;
                if (inf & 0x10000) {
                    int kj = inf & 255;
                    int rj = (inf >> 8) & 255;
                    float aLo = fmaf(c[u][e], SCALE_Q, sB[wp][keyLo - kj]);
                    float aHi = fmaf(c[u][2 + e], SCALE_Q, sB[wp][keyHi - kj]);
                    if (rj != regLo) aLo -= 100.0f;
                    if (rj != regHi) aHi -= 100.0f;
                    pLo = __expf(aLo);
                    pHi = __expf(aHi);
                } else {
                    pLo = 0.0f; pHi = 0.0f;
                }
                c[u][e]     = pLo;  sumLo += pLo;
                c[u][2 + e] = pHi;  sumHi += pHi;
            }
        }
        sumLo += __shfl_xor_sync(0xffffffffu, sumLo, 1);
        sumLo += __shfl_xor_sync(0xffffffffu, sumLo, 2);
        sumHi += __shfl_xor_sync(0xffffffffu, sumHi, 1);
        sumHi += __shfl_xor_sync(0xffffffffu, sumHi, 2);
        float dLo = 1.0f / sumLo;
        float dHi = 1.0f / sumHi;

        uint32_t pa[4][4];
#pragma unroll
        for (int t = 0; t < 4; t++) {
            pa[t][0] = pack2_bf16(c[2 * t][0] * dLo,     c[2 * t][1] * dLo);
            pa[t][1] = pack2_bf16(c[2 * t][2] * dHi,     c[2 * t][3] * dHi);
            pa[t][2] = pack2_bf16(c[2 * t + 1][0] * dLo, c[2 * t + 1][1] * dLo);
            pa[t][3] = pack2_bf16(c[2 * t + 1][2] * dHi, c[2 * t + 1][3] * dHi);
        }

        float o[4][4] = {};
#pragma unroll
        for (int ks = 0; ks < 4; ks++) {
            uint32_t vf[2][4];
#pragma unroll
            for (int half = 0; half < 2; half++)
                ldsm4t(vf[half], &sV[wp][(ks * 16 + (lane & 7) + ((lane >> 3) & 1) * 8) * ATS
                                         + half * 16 + (lane >> 4) * 8]);
            mma_bf16(o[0], pa[ks], vf[0][0], vf[0][1]);
            mma_bf16(o[1], pa[ks], vf[0][2], vf[0][3]);
            mma_bf16(o[2], pa[ks], vf[1][0], vf[1][1]);
            mma_bf16(o[3], pa[ks], vf[1][2], vf[1][3]);
        }

        if (r0 < 49) {
            __nv_bfloat16* p = out + (size_t)(wbase + r0) * 256 + h * 32 + q2;
#pragma unroll
            for (int on = 0; on < 4; on++)
                *(uint32_t*)(p + on * 8) = pack2_bf16(o[on][0], o[on][1]);
        }
        if (r1 < 49) {
            __nv_bfloat16* p = out + (size_t)(wbase + r1) * 256 + h * 32 + q2;
#pragma unroll
            for (int on = 0; on < 4; on++)
                *(uint32_t*)(p + on * 8) = pack2_bf16(o[on][2], o[on][3]);
        }
    }
}

// ---------------------------------------------------------------------------
// Host launcher (graph-capturable: kernel launches only)
// ---------------------------------------------------------------------------
extern "C" void kernel_launch(void* const* d_in, const int* in_sizes, int n_in,
                              void* d_out, int out_size) {
    (void)in_sizes; (void)n_in; (void)out_size;

    const float* x          = (const float*)d_in[0];
    const float* n1g        = (const float*)d_in[1];
    const float* n1b        = (const float*)d_in[2];
    const float* qkv_w      = (const float*)d_in[3];
    const float* qkv_b      = (const float*)d_in[4];
    const float* proj_w     = (const float*)d_in[5];
    const float* proj_b     = (const float*)d_in[6];
    const float* bias_table = (const float*)d_in[7];
    const float* n2g        = (const float*)d_in[8];
    const float* n2b        = (const float*)d_in[9];
    const float* w1         = (const float*)d_in[10];
    const float* b1         = (const float*)d_in[11];
    const float* w2         = (const float*)d_in[12];
    const float* b2         = (const float*)d_in[13];
    float* out = (float*)d_out;

    __nv_bfloat16 *ywin, *qkvb, *attnb, *h2, *act, *wbf;
    float *x1;
    cudaGetSymbolAddress((void**)&ywin,  g_ywin);
    cudaGetSymbolAddress((void**)&qkvb,  g_qkv);
    cudaGetSymbolAddress((void**)&attnb, g_attn);
    cudaGetSymbolAddress((void**)&x1,    g_x1);
    cudaGetSymbolAddress((void**)&h2,    g_h2);
    cudaGetSymbolAddress((void**)&act,   g_act);
    cudaGetSymbolAddress((void**)&wbf,   g_wbf);

    cudaFuncSetAttribute(gemm_wide<EPI_BIAS, true>,
                         cudaFuncAttributeMaxDynamicSharedMemorySize, WIDE_SMEM);
    cudaFuncSetAttribute(gemm_wide<EPI_GELU, true>,
                         cudaFuncAttributeMaxDynamicSharedMemorySize, WIDE_SMEM);
    cudaFuncSetAttribute(gemm_wide<EPI_MLP2, false>,
                         cudaFuncAttributeMaxDynamicSharedMemorySize, WIDE_SMEM);
    cudaFuncSetAttribute(gemm_proj_ln,
                         cudaFuncAttributeMaxDynamicSharedMemorySize, PROJ_SMEM);

    const int lnBlocks = NROWS / 8;

    // 0) weights -> bf16
    wconv_kernel<<<768, 1024>>>(qkv_w, proj_w, w1, w2, wbf);
    // 1) LN1 + cyclic shift + window partition -> bf16
    ln_kernel<<<lnBlocks, 256>>>(x, n1g, n1b, ywin);
    // 2) QKV: [100352,256] @ [256,768] -> bf16
    gemm_wide<EPI_BIAS, true><<<dim3(784, 3), 256, WIDE_SMEM>>>(ywin, wbf + WOFF_QKV,
                                                                qkv_b, qkvb, nullptr, 768, 256);
    // 3) windowed attention (tensor cores) -> bf16
    attn_tc<<<NWIN * 4, 64>>>(qkvb, bias_table, attnb);
    // 4) proj + window-reverse + un-shift + residual + LN2 (fused) -> x1, h2
    gemm_proj_ln<<<1568, 256, PROJ_SMEM>>>(attnb, wbf + WOFF_PROJ, proj_b,
                                           x, n2g, n2b, x1, h2);
    // 5) MLP up + GELU: [100352,256] @ [256,1024] -> bf16
    gemm_wide<EPI_GELU, true><<<dim3(784, 4), 256, WIDE_SMEM>>>(h2, wbf + WOFF_W1,
                                                                b1, act, nullptr, 1024, 256);
    // 6) MLP down + residual -> d_out (fp32): [100352,1024] @ [1024,256]
    //    BN=256 => act (205 MB, not L2-resident) is read from DRAM exactly once.
    gemm_wide<EPI_MLP2, false><<<dim3(784, 1), 256, WIDE_SMEM>>>(act, wbf + WOFF_W2,
                                                                 b2, out, x1, 256, 1024);
}

// round 14
// speedup vs baseline: 1.1686x; 1.1686x over previous
#include <cuda_runtime.h>
#include <cuda_bf16.h>
#include <cstddef>
#include <cstdint>

// ---------------------------------------------------------------------------
// Problem constants
// ---------------------------------------------------------------------------
#define NROWS   100352            // 32 * 56 * 56 tokens
#define NWIN    2048              // 32 * 64 windows
#define SCALE_Q 0.17677669529663689f   // 32^-0.5

// ---------------------------------------------------------------------------
// Scratch (static __device__ arrays; allocation is forbidden)
// ---------------------------------------------------------------------------
__device__ __align__(16) __nv_bfloat16 g_ywin[100352 * 256];   // LN1 out (win order)
__device__ __align__(16) __nv_bfloat16 g_qkv [100352 * 768];   // qkv, bf16
__device__ __align__(16) __nv_bfloat16 g_attn[100352 * 256];   // attention out
__device__ float                       g_x1  [100352 * 256];   // shortcut + proj
__device__ __align__(16) __nv_bfloat16 g_h2  [100352 * 256];   // LN2 out
__device__ __align__(16) __nv_bfloat16 g_act [100352 * 1024];  // gelu(mlp1)
__device__ __align__(16) __nv_bfloat16 g_wbf [786432];         // all 4 weights, bf16

#define WOFF_QKV  0
#define WOFF_PROJ 196608
#define WOFF_W1   262144
#define WOFF_W2   524288

// ---------------------------------------------------------------------------
// window-order row <-> x-order row mapping (shift = 3, 8x8 windows of 7x7)
// ---------------------------------------------------------------------------
__device__ __forceinline__ int win_to_x_row(int m) {
    int w  = m / 49;
    int t  = m - w * 49;
    int b  = w >> 6;
    int wi = w & 63;
    int tr = t / 7;
    int tc = t - tr * 7;
    int gr = ((wi >> 3) * 7) + tr;
    int gc = ((wi & 7) * 7) + tc;
    int r = gr + 3; if (r >= 56) r -= 56;
    int c = gc + 3; if (c >= 56) c -= 56;
    return b * 3136 + r * 56 + c;
}

__device__ __forceinline__ float gelu_tanh(float x) {
    float x3 = x * x * x;
    return 0.5f * x * (1.0f + tanhf(0.7978845608028654f * (x + 0.044715f * x3)));
}

__device__ __forceinline__ uint2 pack4_bf16(float4 v) {
    __nv_bfloat162 lo = __floats2bfloat162_rn(v.x, v.y);
    __nv_bfloat162 hi = __floats2bfloat162_rn(v.z, v.w);
    uint2 r;
    r.x = *(uint32_t*)&lo;
    r.y = *(uint32_t*)&hi;
    return r;
}

__device__ __forceinline__ uint32_t pack2_bf16(float a, float b) {
    __nv_bfloat162 t = __floats2bfloat162_rn(a, b);
    return *(uint32_t*)&t;
}

// ---------------------------------------------------------------------------
// PTX helpers
// ---------------------------------------------------------------------------
__device__ __forceinline__ void ldsm4(uint32_t r[4], const void* p) {
    uint32_t a = (uint32_t)__cvta_generic_to_shared(p);
    asm("ldmatrix.sync.aligned.m8n8.x4.shared.b16 {%0,%1,%2,%3}, [%4];"
        : "=r"(r[0]), "=r"(r[1]), "=r"(r[2]), "=r"(r[3]) : "r"(a) : "memory");
}
__device__ __forceinline__ void ldsm4t(uint32_t r[4], const void* p) {
    uint32_t a = (uint32_t)__cvta_generic_to_shared(p);
    asm("ldmatrix.sync.aligned.m8n8.x4.trans.shared.b16 {%0,%1,%2,%3}, [%4];"
        : "=r"(r[0]), "=r"(r[1]), "=r"(r[2]), "=r"(r[3]) : "r"(a) : "memory");
}
__device__ __forceinline__ void mma_bf16(float c[4], const uint32_t a[4],
                                         uint32_t b0, uint32_t b1) {
    asm("mma.sync.aligned.m16n8k16.row.col.f32.bf16.bf16.f32 "
        "{%0,%1,%2,%3}, {%4,%5,%6,%7}, {%8,%9}, {%0,%1,%2,%3};"
        : "+f"(c[0]), "+f"(c[1]), "+f"(c[2]), "+f"(c[3])
        : "r"(a[0]), "r"(a[1]), "r"(a[2]), "r"(a[3]), "r"(b0), "r"(b1));
}
__device__ __forceinline__ void cpasync16(void* dst, const void* src) {
    uint32_t d = (uint32_t)__cvta_generic_to_shared(dst);
    asm volatile("cp.async.cg.shared.global [%0], [%1], 16;" :: "r"(d), "l"(src));
}
__device__ __forceinline__ void cp_commit() {
    asm volatile("cp.async.commit_group;");
}
template <int N>
__device__ __forceinline__ void cp_wait() {
    asm volatile("cp.async.wait_group %0;" :: "n"(N));
}

// ---------------------------------------------------------------------------
// Weight conversion: fp32 -> bf16, once per launch
// ---------------------------------------------------------------------------
__global__ void __launch_bounds__(1024) wconv_kernel(const float* __restrict__ qkv_w,
                                                     const float* __restrict__ proj_w,
                                                     const float* __restrict__ w1,
                                                     const float* __restrict__ w2,
                                                     __nv_bfloat16* __restrict__ dst) {
    int i = blockIdx.x * 1024 + threadIdx.x;   // grid = 768
    float v;
    if      (i < WOFF_PROJ) v = qkv_w[i];
    else if (i < WOFF_W1)   v = proj_w[i - WOFF_PROJ];
    else if (i < WOFF_W2)   v = w1[i - WOFF_W1];
    else                    v = w2[i - WOFF_W2];
    dst[i] = __float2bfloat16(v);
}

// ---------------------------------------------------------------------------
// LayerNorm (LN1 only): one warp per 256-wide row, gather + bf16 output.
// ---------------------------------------------------------------------------
__global__ void __launch_bounds__(256) ln_kernel(const float* __restrict__ in,
                                                 const float* __restrict__ gamma,
                                                 const float* __restrict__ beta,
                                                 __nv_bfloat16* __restrict__ out) {
    int gw   = (blockIdx.x * blockDim.x + threadIdx.x) >> 5;
    int lane = threadIdx.x & 31;
    if (gw >= NROWS) return;
    int src = win_to_x_row(gw);

    const float4* row = (const float4*)(in + (size_t)src * 256);
    float4 v0 = row[lane];
    float4 v1 = row[lane + 32];

    float s  = v0.x + v0.y + v0.z + v0.w + v1.x + v1.y + v1.z + v1.w;
    float ss = v0.x*v0.x + v0.y*v0.y + v0.z*v0.z + v0.w*v0.w
             + v1.x*v1.x + v1.y*v1.y + v1.z*v1.z + v1.w*v1.w;
#pragma unroll
    for (int o = 16; o; o >>= 1) {
        s  += __shfl_xor_sync(0xffffffffu, s,  o);
        ss += __shfl_xor_sync(0xffffffffu, ss, o);
    }
    float mu  = s * (1.0f / 256.0f);
    float inv = rsqrtf(ss * (1.0f / 256.0f) - mu * mu + 1e-5f);

    float4 g0 = ((const float4*)gamma)[lane];
    float4 g1 = ((const float4*)gamma)[lane + 32];
    float4 b0 = ((const float4*)beta)[lane];
    float4 b1 = ((const float4*)beta)[lane + 32];

    float4 o0, o1;
    o0.x = (v0.x - mu) * inv * g0.x + b0.x;
    o0.y = (v0.y - mu) * inv * g0.y + b0.y;
    o0.z = (v0.z - mu) * inv * g0.z + b0.z;
    o0.w = (v0.w - mu) * inv * g0.w + b0.w;
    o1.x = (v1.x - mu) * inv * g1.x + b1.x;
    o1.y = (v1.y - mu) * inv * g1.y + b1.y;
    o1.z = (v1.z - mu) * inv * g1.z + b1.z;
    o1.w = (v1.w - mu) * inv * g1.w + b1.w;

    uint2* orow = (uint2*)(out + (size_t)gw * 256);
    orow[lane]      = pack4_bf16(o0);
    orow[lane + 32] = pack4_bf16(o1);
}

// ---------------------------------------------------------------------------
// bf16 tensor-core GEMM, BK=64, 3-stage pipeline + register fragment
// double-buffering (R9/R11 champion mainloop).
// GRID MAPPING: blockIdx.x = n-block, blockIdx.y = m-block, so the first
// scheduling wave covers all n-blocks of each m-tile -> A tile re-reads hit
// L2 (matters for MLP2 where A = 205 MB, not L2-resident).
// ---------------------------------------------------------------------------
#define EPI_BIAS 0
#define EPI_GELU 1
#define EPI_MLP2 3

#define AS 72
#define BSS 136
#define A_STG (128 * AS)
#define B_STG (64 * BSS)
#define GEMM_SMEM ((3 * A_STG + 3 * B_STG) * 2)   // 107520 bytes

template <int EPI, bool OUT_BF16>
__global__ void __launch_bounds__(256, 2) gemm_bf16(const __nv_bfloat16* __restrict__ A,
                                                    const __nv_bfloat16* __restrict__ B,
                                                    const float* __restrict__ bias,
                                                    void* __restrict__ Cout,
                                                    const float* __restrict__ res,
                                                    int N, int K) {
    extern __shared__ __align__(16) __nv_bfloat16 smp[];
    __nv_bfloat16* Asm = smp;
    __nv_bfloat16* Bsm = smp + 3 * A_STG;

    const int tid  = threadIdx.x;
    const int lane = tid & 31;
    const int wid  = tid >> 5;
    const int bm   = blockIdx.y * 128;   // m = grid.y (n iterates fastest)
    const int bn   = blockIdx.x * 128;
    const int wm   = (wid & 3) * 32;
    const int wn   = (wid >> 2) * 64;

    const __nv_bfloat16* Ab = A + (size_t)bm * K;
    const __nv_bfloat16* Bb = B + bn;

    float acc[2][8][4] = {};

    auto load_tile = [&](int k0, int stg) {
        __nv_bfloat16* as = Asm + stg * A_STG;
        __nv_bfloat16* bs = Bsm + stg * B_STG;
#pragma unroll
        for (int i = 0; i < 4; i++) {
            int c = tid + i * 256;
            int row = c >> 3, kc = (c & 7) * 8;
            cpasync16(&as[row * AS + kc], Ab + (size_t)row * K + k0 + kc);
        }
#pragma unroll
        for (int i = 0; i < 4; i++) {
            int c = tid + i * 256;
            int k = c >> 4, n = (c & 15) * 8;
            cpasync16(&bs[k * BSS + n], Bb + (size_t)(k0 + k) * N + n);
        }
        cp_commit();
    };

    const int nIter = K >> 6;
    load_tile(0, 0);
    load_tile(64, 1);

    const int aoff0 = (wm + (lane & 15)) * AS + (lane >> 4) * 8;
    const int aoff1 = aoff0 + 16 * AS;
    const int boff  = ((lane & 7) + ((lane >> 3) & 1) * 8) * BSS
                      + wn + (lane >> 4) * 8;

    for (int i = 0; i < nIter; i++) {
        if (i + 1 < nIter) cp_wait<1>(); else cp_wait<0>();
        __syncthreads();
        if (i + 2 < nIter) load_tile((i + 2) * 64, (i + 2) % 3);

        const __nv_bfloat16* as = Asm + (i % 3) * A_STG;
        const __nv_bfloat16* bs = Bsm + (i % 3) * B_STG;
        const __nv_bfloat16* a0 = as + aoff0;
        const __nv_bfloat16* a1 = as + aoff1;
        const __nv_bfloat16* bp = bs + boff;

        uint32_t af[2][2][4];
        uint32_t bf[2][4];
        ldsm4(af[0][0], a0);
        ldsm4(af[0][1], a1);
        ldsm4t(bf[0], bp);
#pragma unroll
        for (int s = 0; s < 16; s++) {
            const int ks = (s >> 2) * 16;
            const int np = s & 3;
            const int ca = (s >> 2) & 1;
            const int cb = s & 1;
            if (np == 2 && ks < 48) {
                ldsm4(af[ca ^ 1][0], a0 + ks + 16);
                ldsm4(af[ca ^ 1][1], a1 + ks + 16);
            }
            if (s < 15) {
                const int ns = s + 1;
                ldsm4t(bf[cb ^ 1], bp + ((ns >> 2) * 16) * BSS + (ns & 3) * 16);
            }
            mma_bf16(acc[0][np * 2 + 0], af[ca][0], bf[cb][0], bf[cb][1]);
            mma_bf16(acc[1][np * 2 + 0], af[ca][1], bf[cb][0], bf[cb][1]);
            mma_bf16(acc[0][np * 2 + 1], af[ca][0], bf[cb][2], bf[cb][3]);
            mma_bf16(acc[1][np * 2 + 1], af[ca][1], bf[cb][2], bf[cb][3]);
        }
    }

    // ---------------- epilogue ----------------
    float bv0[8], bv1[8];
#pragma unroll
    for (int ni = 0; ni < 8; ni++) {
        int c = bn + wn + ni * 8 + 2 * (lane & 3);
        bv0[ni] = bias[c];
        bv1[ni] = bias[c + 1];
    }

#pragma unroll
    for (int mi = 0; mi < 2; mi++) {
#pragma unroll
        for (int half = 0; half < 2; half++) {
            int r = bm + wm + mi * 16 + (lane >> 2) + half * 8;
            size_t rowoff = (size_t)r * N;
#pragma unroll
            for (int ni = 0; ni < 8; ni++) {
                int c = bn + wn + ni * 8 + 2 * (lane & 3);
                float v0 = acc[mi][ni][half * 2 + 0] + bv0[ni];
                float v1 = acc[mi][ni][half * 2 + 1] + bv1[ni];
                if (EPI == EPI_GELU) { v0 = gelu_tanh(v0); v1 = gelu_tanh(v1); }
                if (EPI == EPI_MLP2) {
                    float2 rr = *(const float2*)(res + rowoff + c);
                    v0 += rr.x; v1 += rr.y;
                }
                if (OUT_BF16) {
                    __nv_bfloat162 w = __floats2bfloat162_rn(v0, v1);
                    *(__nv_bfloat162*)((__nv_bfloat16*)Cout + rowoff + c) = w;
                } else {
                    float2 w = {v0, v1};
                    *(float2*)((float*)Cout + rowoff + c) = w;
                }
            }
        }
    }
}

// ---------------------------------------------------------------------------
// PROJ + residual + LN2 fused GEMM (unchanged from R10/R11).
// ---------------------------------------------------------------------------
#define PS_AS 40
#define PS_BS 264
#define PS_A_STG (64 * PS_AS)
#define PS_B_STG (32 * PS_BS)
#define PROJ_SMEM ((4 * PS_A_STG + 4 * PS_B_STG) * 2)   // 88064

__global__ void __launch_bounds__(256, 2) gemm_proj_ln(
    const __nv_bfloat16* __restrict__ A,     // attn out (window order)
    const __nv_bfloat16* __restrict__ B,     // proj_w bf16 [k][n]
    const float* __restrict__ bias,
    const float* __restrict__ xres,          // original input x
    const float* __restrict__ gamma,         // norm2_g
    const float* __restrict__ beta,          // norm2_b
    float* __restrict__ x1,
    __nv_bfloat16* __restrict__ h2) {
    extern __shared__ __align__(16) __nv_bfloat16 smp[];
    __nv_bfloat16* Asm = smp;
    __nv_bfloat16* Bsm = smp + 4 * PS_A_STG;

    const int tid  = threadIdx.x;
    const int lane = tid & 31;
    const int wid  = tid >> 5;
    const int bm   = blockIdx.x * 64;
    const int wm   = (wid & 1) * 32;
    const int wn   = (wid >> 1) * 64;
    const int K = 256, N = 256;

    const __nv_bfloat16* Ab = A + (size_t)bm * K;

    float acc[2][8][4] = {};

    auto load_tile = [&](int k0, int stg) {
        __nv_bfloat16* as = Asm + stg * PS_A_STG;
        __nv_bfloat16* bs = Bsm + stg * PS_B_STG;
        {
            int row = tid >> 2, kc = (tid & 3) * 8;      // A: 64x32
            cpasync16(&as[row * PS_AS + kc], Ab + (size_t)row * K + k0 + kc);
        }
#pragma unroll
        for (int i = 0; i < 4; i++) {                    // B: 32x256
            int c = tid + i * 256;
            int k = c >> 5, n = (c & 31) * 8;
            cpasync16(&bs[k * PS_BS + n], B + (size_t)(k0 + k) * N + n);
        }
        cp_commit();
    };

    const int nIter = 8;                                 // K/32
    load_tile(0, 0);
    load_tile(32, 1);
    load_tile(64, 2);

    for (int i = 0; i < nIter; i++) {
        if      (i + 2 < nIter) cp_wait<2>();
        else if (i + 1 < nIter) cp_wait<1>();
        else                    cp_wait<0>();
        __syncthreads();
        if (i + 3 < nIter) load_tile((i + 3) * 32, (i + 3) & 3);

        const __nv_bfloat16* as = Asm + (i & 3) * PS_A_STG;
        const __nv_bfloat16* bs = Bsm + (i & 3) * PS_B_STG;
#pragma unroll
        for (int ks = 0; ks < 32; ks += 16) {
            uint32_t af[2][4];
#pragma unroll
            for (int mi = 0; mi < 2; mi++)
                ldsm4(af[mi], as + (wm + mi * 16 + (lane & 15)) * PS_AS
                                 + ks + (lane >> 4) * 8);
#pragma unroll
            for (int np = 0; np < 4; np++) {
                uint32_t bf[4];
                ldsm4t(bf, bs + (ks + (lane & 7) + ((lane >> 3) & 1) * 8) * PS_BS
                              + wn + np * 16 + (lane >> 4) * 8);
                mma_bf16(acc[0][np * 2 + 0], af[0], bf[0], bf[1]);
                mma_bf16(acc[1][np * 2 + 0], af[1], bf[0], bf[1]);
                mma_bf16(acc[0][np * 2 + 1], af[0], bf[2], bf[3]);
                mma_bf16(acc[1][np * 2 + 1], af[1], bf[2], bf[3]);
            }
        }
    }
    __syncthreads();   // all warps done with pipeline smem before x1 staging

    // ---------------- epilogue: x1 = acc + bias + x, staged in smem ----------
    float* x1s = (float*)smp;        // 64 rows x stride 264 fp32
    const int S = 264;

    float bv0[8], bv1[8];
#pragma unroll
    for (int ni = 0; ni < 8; ni++) {
        int c = wn + ni * 8 + 2 * (lane & 3);
        bv0[ni] = bias[c];
        bv1[ni] = bias[c + 1];
    }

#pragma unroll
    for (int mi = 0; mi < 2; mi++) {
#pragma unroll
        for (int half = 0; half < 2; half++) {
            int row  = wm + mi * 16 + (lane >> 2) + half * 8;   // 0..63
            int xrow = win_to_x_row(bm + row);
            size_t off = (size_t)xrow * 256;
#pragma unroll
            for (int ni = 0; ni < 8; ni++) {
                int c = wn + ni * 8 + 2 * (lane & 3);
                float v0 = acc[mi][ni][half * 2 + 0] + bv0[ni];
                float v1 = acc[mi][ni][half * 2 + 1] + bv1[ni];
                float2 rr = *(const float2*)(xres + off + c);
                v0 += rr.x; v1 += rr.y;
                float2 w = {v0, v1};
                *(float2*)(x1 + off + c)      = w;
                *(float2*)(&x1s[row * S + c]) = w;
            }
        }
    }
    __syncthreads();

    // ---------------- in-block LN2: 8 rows per warp -> h2 bf16 ---------------
    float4 g0 = *(const float4*)(gamma + lane * 8);
    float4 g1 = *(const float4*)(gamma + lane * 8 + 4);
    float4 be0 = *(const float4*)(beta + lane * 8);
    float4 be1 = *(const float4*)(beta + lane * 8 + 4);

#pragma unroll
    for (int rr = 0; rr < 8; rr++) {
        int row = wid * 8 + rr;
        float4 u0 = *(const float4*)(&x1s[row * S + lane * 8]);
        float4 u1 = *(const float4*)(&x1s[row * S + lane * 8 + 4]);

        float s  = u0.x + u0.y + u0.z + u0.w + u1.x + u1.y + u1.z + u1.w;
        float ss = u0.x*u0.x + u0.y*u0.y + u0.z*u0.z + u0.w*u0.w
                 + u1.x*u1.x + u1.y*u1.y + u1.z*u1.z + u1.w*u1.w;
#pragma unroll
        for (int o = 16; o; o >>= 1) {
            s  += __shfl_xor_sync(0xffffffffu, s,  o);
            ss += __shfl_xor_sync(0xffffffffu, ss, o);
        }
        float mu  = s * (1.0f / 256.0f);
        float inv = rsqrtf(ss * (1.0f / 256.0f) - mu * mu + 1e-5f);

        float4 o0, o1;
        o0.x = (u0.x - mu) * inv * g0.x + be0.x;
        o0.y = (u0.y - mu) * inv * g0.y + be0.y;
        o0.z = (u0.z - mu) * inv * g0.z + be0.z;
        o0.w = (u0.w - mu) * inv * g0.w + be0.w;
        o1.x = (u1.x - mu) * inv * g1.x + be1.x;
        o1.y = (u1.y - mu) * inv * g1.y + be1.y;
        o1.z = (u1.z - mu) * inv * g1.z + be1.z;
        o1.w = (u1.w - mu) * inv * g1.w + be1.w;

        int xrow = win_to_x_row(bm + row);
        uint2 p0 = pack4_bf16(o0);
        uint2 p1 = pack4_bf16(o1);
        uint4 pk = make_uint4(p0.x, p0.y, p1.x, p1.y);
        *(uint4*)(h2 + (size_t)xrow * 256 + lane * 8) = pk;
    }
}

// ---------------------------------------------------------------------------
// Tensor-core windowed attention (R11 occupancy-tuned version; unchanged).
// ---------------------------------------------------------------------------
#define ATS 40

__global__ void __launch_bounds__(64) attn_tc(const __nv_bfloat16* __restrict__ qkv,
                                              const float* __restrict__ bias_table,
                                              __nv_bfloat16* __restrict__ out) {
    __shared__ __align__(16) __nv_bfloat16 sK[2][64 * ATS];
    __shared__ __align__(16) __nv_bfloat16 sV[2][64 * ATS];
    __shared__ float sB[2][169];
    __shared__ int   sInfo[64];

    const int w     = blockIdx.x >> 2;
    const int wp    = threadIdx.x >> 5;
    const int lane  = threadIdx.x & 31;
    const int h     = (blockIdx.x & 3) * 2 + wp;
    const int wbase = w * 49;
    const int wi    = w & 63;

    if (threadIdx.x < 64) {
        int j = threadIdx.x;
        int info;
        if (j < 49) {
            int rj = j / 7, cj = j - (j / 7) * 7;
            int gr = (wi >> 3) * 7 + rj;
            int gc = (wi & 7) * 7 + cj;
            int rh = (gr < 49) ? 0 : ((gr < 53) ? 1 : 2);
            int rc = (gc < 49) ? 0 : ((gc < 53) ? 1 : 2);
            int key = rj + 13 * cj;
            info = key | ((rh * 3 + rc) << 8) | (1 << 16);
        } else {
            info = 0 | (255 << 8);
        }
        sInfo[j] = info;
    }

    for (int idx = lane; idx < 169; idx += 32) sB[wp][idx] = bias_table[idx * 8 + h];

    // K/V rows 0..48 from gmem (coalesced 16B chunks)
    for (int tsk = lane; tsk < 196; tsk += 32) {
        int row = tsk >> 2, seg = (tsk & 3) * 8;
        const __nv_bfloat16* base = qkv + (size_t)(wbase + row) * 768 + h * 32 + seg;
        int off = row * ATS + seg;
        *(uint4*)&sK[wp][off] = *(const uint4*)(base + 256);
        *(uint4*)&sV[wp][off] = *(const uint4*)(base + 512);
    }
    // zero pad rows 49..63
    for (int z = lane; z < 60; z += 32) {
        int row = 49 + (z >> 2), seg = (z & 3) * 8;
        int off = row * ATS + seg;
        uint4 zz = make_uint4(0, 0, 0, 0);
        *(uint4*)&sK[wp][off] = zz;
        *(uint4*)&sV[wp][off] = zz;
    }
    __syncthreads();

    const int q2 = 2 * (lane & 3);
    const int r = lane >> 2;
    const __nv_bfloat16* qb = qkv + (size_t)wbase * 768 + h * 32;   // row stride 768

#pragma unroll
    for (int mt = 0; mt < 4; mt++) {
        const int r0 = mt * 16 + r;
        const int r1 = r0 + 8;
        const bool v0 = (r0 < 49), v1 = (r1 < 49);
        uint32_t qf[2][4];
#pragma unroll
        for (int ks = 0; ks < 2; ks++) {
            const int cc = q2 + ks * 16;
            qf[ks][0] = v0 ? *(const uint32_t*)(qb + (size_t)r0 * 768 + cc)     : 0u;
            qf[ks][1] = v1 ? *(const uint32_t*)(qb + (size_t)r1 * 768 + cc)     : 0u;
            qf[ks][2] = v0 ? *(const uint32_t*)(qb + (size_t)r0 * 768 + cc + 8) : 0u;
            qf[ks][3] = v1 ? *(const uint32_t*)(qb + (size_t)r1 * 768 + cc + 8) : 0u;
        }

        float c[8][4] = {};
#pragma unroll
        for (int nt = 0; nt < 4; nt++) {
#pragma unroll
            for (int ks = 0; ks < 2; ks++) {
                uint32_t kf[4];
                ldsm4(kf, &sK[wp][(nt * 16 + (lane & 7) + ((lane >> 4) & 1) * 8) * ATS
                                  + ks * 16 + ((lane >> 3) & 1) * 8]);
                mma_bf16(c[2 * nt + 0], qf[ks], kf[0], kf[1]);
                mma_bf16(c[2 * nt + 1], qf[ks], kf[2], kf[3]);
            }
        }

        int infLo = sInfo[r0 < 64 ? r0 : 0], infHi = sInfo[r1 < 64 ? r1 : 0];
        int keyLo = (infLo & 255) + 84, regLo = (infLo >> 8) & 255;
        int keyHi = (infHi & 255) + 84, regHi = (infHi >> 8) & 255;

        float sumLo = 0.0f, sumHi = 0.0f;
#pragma unroll
        for (int u = 0; u < 8; u++) {
#pragma unroll
            for (int e = 0; e < 2; e++) {
                int inf = sInfo[u * 8 + q2 + e];
                float pLo, pHi;
                if (inf & 0x10000) {
                    int kj = inf & 255;
                    int rj = (inf >> 8) & 255;
                    float aLo = fmaf(c[u][e], SCALE_Q, sB[wp][keyLo - kj]);
                    float aHi = fmaf(c[u][2 + e], SCALE_Q, sB[wp][keyHi - kj]);
                    if (rj != regLo) aLo -= 100.0f;
                    if (rj != regHi) aHi -= 100.0f;
                    pLo = __expf(aLo);
                    pHi = __expf(aHi);
                } else {
                    pLo = 0.0f; pHi = 0.0f;
                }
                c[u][e]     = pLo;  sumLo += pLo;
                c[u][2 + e] = pHi;  sumHi += pHi;
            }
        }
        sumLo += __shfl_xor_sync(0xffffffffu, sumLo, 1);
        sumLo += __shfl_xor_sync(0xffffffffu, sumLo, 2);
        sumHi += __shfl_xor_sync(0xffffffffu, sumHi, 1);
        sumHi += __shfl_xor_sync(0xffffffffu, sumHi, 2);
        float dLo = 1.0f / sumLo;
        float dHi = 1.0f / sumHi;

        uint32_t pa[4][4];
#pragma unroll
        for (int t = 0; t < 4; t++) {
            pa[t][0] = pack2_bf16(c[2 * t][0] * dLo,     c[2 * t][1] * dLo);
            pa[t][1] = pack2_bf16(c[2 * t][2] * dHi,     c[2 * t][3] * dHi);
            pa[t][2] = pack2_bf16(c[2 * t + 1][0] * dLo, c[2 * t + 1][1] * dLo);
            pa[t][3] = pack2_bf16(c[2 * t + 1][2] * dHi, c[2 * t + 1][3] * dHi);
        }

        float o[4][4] = {};
#pragma unroll
        for (int ks = 0; ks < 4; ks++) {
            uint32_t vf[2][4];
#pragma unroll
            for (int half = 0; half < 2; half++)
                ldsm4t(vf[half], &sV[wp][(ks * 16 + (lane & 7) + ((lane >> 3) & 1) * 8) * ATS
                                         + half * 16 + (lane >> 4) * 8]);
            mma_bf16(o[0], pa[ks], vf[0][0], vf[0][1]);
            mma_bf16(o[1], pa[ks], vf[0][2], vf[0][3]);
            mma_bf16(o[2], pa[ks], vf[1][0], vf[1][1]);
            mma_bf16(o[3], pa[ks], vf[1][2], vf[1][3]);
        }

        if (r0 < 49) {
            __nv_bfloat16* p = out + (size_t)(wbase + r0) * 256 + h * 32 + q2;
#pragma unroll
            for (int on = 0; on < 4; on++)
                *(uint32_t*)(p + on * 8) = pack2_bf16(o[on][0], o[on][1]);
        }
        if (r1 < 49) {
            __nv_bfloat16* p = out + (size_t)(wbase + r1) * 256 + h * 32 + q2;
#pragma unroll
            for (int on = 0; on < 4; on++)
                *(uint32_t*)(p + on * 8) = pack2_bf16(o[on][2], o[on][3]);
        }
    }
}

// ---------------------------------------------------------------------------
// Host launcher (graph-capturable: kernel launches only)
// ---------------------------------------------------------------------------
extern "C" void kernel_launch(void* const* d_in, const int* in_sizes, int n_in,
                              void* d_out, int out_size) {
    (void)in_sizes; (void)n_in; (void)out_size;

    const float* x          = (const float*)d_in[0];
    const float* n1g        = (const float*)d_in[1];
    const float* n1b        = (const float*)d_in[2];
    const float* qkv_w      = (const float*)d_in[3];
    const float* qkv_b      = (const float*)d_in[4];
    const float* proj_w     = (const float*)d_in[5];
    const float* proj_b     = (const float*)d_in[6];
    const float* bias_table = (const float*)d_in[7];
    const float* n2g        = (const float*)d_in[8];
    const float* n2b        = (const float*)d_in[9];
    const float* w1         = (const float*)d_in[10];
    const float* b1         = (const float*)d_in[11];
    const float* w2         = (const float*)d_in[12];
    const float* b2         = (const float*)d_in[13];
    float* out = (float*)d_out;

    __nv_bfloat16 *ywin, *qkvb, *attnb, *h2, *act, *wbf;
    float *x1;
    cudaGetSymbolAddress((void**)&ywin,  g_ywin);
    cudaGetSymbolAddress((void**)&qkvb,  g_qkv);
    cudaGetSymbolAddress((void**)&attnb, g_attn);
    cudaGetSymbolAddress((void**)&x1,    g_x1);
    cudaGetSymbolAddress((void**)&h2,    g_h2);
    cudaGetSymbolAddress((void**)&act,   g_act);
    cudaGetSymbolAddress((void**)&wbf,   g_wbf);

    cudaFuncSetAttribute(gemm_bf16<EPI_BIAS, true>,
                         cudaFuncAttributeMaxDynamicSharedMemorySize, GEMM_SMEM);
    cudaFuncSetAttribute(gemm_bf16<EPI_GELU, true>,
                         cudaFuncAttributeMaxDynamicSharedMemorySize, GEMM_SMEM);
    cudaFuncSetAttribute(gemm_bf16<EPI_MLP2, false>,
                         cudaFuncAttributeMaxDynamicSharedMemorySize, GEMM_SMEM);
    cudaFuncSetAttribute(gemm_proj_ln,
                         cudaFuncAttributeMaxDynamicSharedMemorySize, PROJ_SMEM);

    const int lnBlocks = NROWS / 8;

    // 0) weights -> bf16
    wconv_kernel<<<768, 1024>>>(qkv_w, proj_w, w1, w2, wbf);
    // 1) LN1 + cyclic shift + window partition -> bf16
    ln_kernel<<<lnBlocks, 256>>>(x, n1g, n1b, ywin);
    // 2) QKV: [100352,256] @ [256,768] -> bf16   (grid: x = n-blocks)
    gemm_bf16<EPI_BIAS, true><<<dim3(6, 784), 256, GEMM_SMEM>>>(ywin, wbf + WOFF_QKV,
                                                                qkv_b, qkvb, nullptr, 768, 256);
    // 3) windowed attention (tensor cores) -> bf16
    attn_tc<<<NWIN * 4, 64>>>(qkvb, bias_table, attnb);
    // 4) proj + window-reverse + un-shift + residual + LN2 (fused) -> x1, h2
    gemm_proj_ln<<<1568, 256, PROJ_SMEM>>>(attnb, wbf + WOFF_PROJ, proj_b,
                                           x, n2g, n2b, x1, h2);
    // 5) MLP up + GELU: [100352,256] @ [256,1024] -> bf16
    gemm_bf16<EPI_GELU, true><<<dim3(8, 784), 256, GEMM_SMEM>>>(h2, wbf + WOFF_W1,
                                                                b1, act, nullptr, 1024, 256);
    // 6) MLP down + residual -> d_out (fp32): [100352,1024] @ [1024,256]
    //    n-blocks in grid.x: both n-tiles of an m-tile run in the same wave,
    //    so the 205 MB act re-read hits L2 instead of DRAM.
    gemm_bf16<EPI_MLP2, false><<<dim3(2, 784), 256, GEMM_SMEM>>>(act, wbf + WOFF_W2,
                                                                 b2, out, x1, 256, 1024);
}

// round 15
// speedup vs baseline: 1.1724x; 1.0033x over previous
#include <cuda_runtime.h>
#include <cuda_bf16.h>
#include <cstddef>
#include <cstdint>

// ---------------------------------------------------------------------------
// Problem constants
// ---------------------------------------------------------------------------
#define NROWS   100352            // 32 * 56 * 56 tokens
#define NWIN    2048              // 32 * 64 windows
#define SCALE_Q 0.17677669529663689f   // 32^-0.5
#define LOG2E   1.4426950408889634f
#define SCALE_Q_L2E (SCALE_Q * LOG2E)
#define MASK_L2E 144.26950408889634f   // 100 * log2(e)

// ---------------------------------------------------------------------------
// Scratch (static __device__ arrays; allocation is forbidden)
// ---------------------------------------------------------------------------
__device__ __align__(16) __nv_bfloat16 g_ywin[100352 * 256];   // LN1 out (win order)
__device__ __align__(16) __nv_bfloat16 g_qkv [100352 * 768];   // qkv, bf16
__device__ __align__(16) __nv_bfloat16 g_attn[100352 * 256];   // attention out
__device__ float                       g_x1  [100352 * 256];   // shortcut + proj
__device__ __align__(16) __nv_bfloat16 g_h2  [100352 * 256];   // LN2 out
__device__ __align__(16) __nv_bfloat16 g_act [100352 * 1024];  // gelu(mlp1)
__device__ __align__(16) __nv_bfloat16 g_wbf [786432];         // all 4 weights, bf16

#define WOFF_QKV  0
#define WOFF_PROJ 196608
#define WOFF_W1   262144
#define WOFF_W2   524288

// ---------------------------------------------------------------------------
// window-order row <-> x-order row mapping (shift = 3, 8x8 windows of 7x7)
// ---------------------------------------------------------------------------
__device__ __forceinline__ int win_to_x_row(int m) {
    int w  = m / 49;
    int t  = m - w * 49;
    int b  = w >> 6;
    int wi = w & 63;
    int tr = t / 7;
    int tc = t - tr * 7;
    int gr = ((wi >> 3) * 7) + tr;
    int gc = ((wi & 7) * 7) + tc;
    int r = gr + 3; if (r >= 56) r -= 56;
    int c = gc + 3; if (c >= 56) c -= 56;
    return b * 3136 + r * 56 + c;
}

__device__ __forceinline__ float gelu_tanh(float x) {
    float x3 = x * x * x;
    return 0.5f * x * (1.0f + tanhf(0.7978845608028654f * (x + 0.044715f * x3)));
}

__device__ __forceinline__ uint2 pack4_bf16(float4 v) {
    __nv_bfloat162 lo = __floats2bfloat162_rn(v.x, v.y);
    __nv_bfloat162 hi = __floats2bfloat162_rn(v.z, v.w);
    uint2 r;
    r.x = *(uint32_t*)&lo;
    r.y = *(uint32_t*)&hi;
    return r;
}

__device__ __forceinline__ uint32_t pack2_bf16(float a, float b) {
    __nv_bfloat162 t = __floats2bfloat162_rn(a, b);
    return *(uint32_t*)&t;
}

__device__ __forceinline__ float ex2f(float x) {
    float y;
    asm("ex2.approx.f32 %0, %1;" : "=f"(y) : "f"(x));
    return y;
}

// ---------------------------------------------------------------------------
// PTX helpers
// ---------------------------------------------------------------------------
__device__ __forceinline__ void ldsm4(uint32_t r[4], const void* p) {
    uint32_t a = (uint32_t)__cvta_generic_to_shared(p);
    asm("ldmatrix.sync.aligned.m8n8.x4.shared.b16 {%0,%1,%2,%3}, [%4];"
        : "=r"(r[0]), "=r"(r[1]), "=r"(r[2]), "=r"(r[3]) : "r"(a) : "memory");
}
__device__ __forceinline__ void ldsm4t(uint32_t r[4], const void* p) {
    uint32_t a = (uint32_t)__cvta_generic_to_shared(p);
    asm("ldmatrix.sync.aligned.m8n8.x4.trans.shared.b16 {%0,%1,%2,%3}, [%4];"
        : "=r"(r[0]), "=r"(r[1]), "=r"(r[2]), "=r"(r[3]) : "r"(a) : "memory");
}
__device__ __forceinline__ void mma_bf16(float c[4], const uint32_t a[4],
                                         uint32_t b0, uint32_t b1) {
    asm("mma.sync.aligned.m16n8k16.row.col.f32.bf16.bf16.f32 "
        "{%0,%1,%2,%3}, {%4,%5,%6,%7}, {%8,%9}, {%0,%1,%2,%3};"
        : "+f"(c[0]), "+f"(c[1]), "+f"(c[2]), "+f"(c[3])
        : "r"(a[0]), "r"(a[1]), "r"(a[2]), "r"(a[3]), "r"(b0), "r"(b1));
}
__device__ __forceinline__ void cpasync16(void* dst, const void* src) {
    uint32_t d = (uint32_t)__cvta_generic_to_shared(dst);
    asm volatile("cp.async.cg.shared.global [%0], [%1], 16;" :: "r"(d), "l"(src));
}
__device__ __forceinline__ void cp_commit() {
    asm volatile("cp.async.commit_group;");
}
template <int N>
__device__ __forceinline__ void cp_wait() {
    asm volatile("cp.async.wait_group %0;" :: "n"(N));
}

// ---------------------------------------------------------------------------
// Weight conversion: fp32 -> bf16, once per launch
// ---------------------------------------------------------------------------
__global__ void __launch_bounds__(1024) wconv_kernel(const float* __restrict__ qkv_w,
                                                     const float* __restrict__ proj_w,
                                                     const float* __restrict__ w1,
                                                     const float* __restrict__ w2,
                                                     __nv_bfloat16* __restrict__ dst) {
    int i = blockIdx.x * 1024 + threadIdx.x;   // grid = 768
    float v;
    if      (i < WOFF_PROJ) v = qkv_w[i];
    else if (i < WOFF_W1)   v = proj_w[i - WOFF_PROJ];
    else if (i < WOFF_W2)   v = w1[i - WOFF_W1];
    else                    v = w2[i - WOFF_W2];
    dst[i] = __float2bfloat16(v);
}

// ---------------------------------------------------------------------------
// LayerNorm (LN1 only): one warp per 256-wide row, gather + bf16 output.
// ---------------------------------------------------------------------------
__global__ void __launch_bounds__(256) ln_kernel(const float* __restrict__ in,
                                                 const float* __restrict__ gamma,
                                                 const float* __restrict__ beta,
                                                 __nv_bfloat16* __restrict__ out) {
    int gw   = (blockIdx.x * blockDim.x + threadIdx.x) >> 5;
    int lane = threadIdx.x & 31;
    if (gw >= NROWS) return;
    int src = win_to_x_row(gw);

    const float4* row = (const float4*)(in + (size_t)src * 256);
    float4 v0 = row[lane];
    float4 v1 = row[lane + 32];

    float s  = v0.x + v0.y + v0.z + v0.w + v1.x + v1.y + v1.z + v1.w;
    float ss = v0.x*v0.x + v0.y*v0.y + v0.z*v0.z + v0.w*v0.w
             + v1.x*v1.x + v1.y*v1.y + v1.z*v1.z + v1.w*v1.w;
#pragma unroll
    for (int o = 16; o; o >>= 1) {
        s  += __shfl_xor_sync(0xffffffffu, s,  o);
        ss += __shfl_xor_sync(0xffffffffu, ss, o);
    }
    float mu  = s * (1.0f / 256.0f);
    float inv = rsqrtf(ss * (1.0f / 256.0f) - mu * mu + 1e-5f);

    float4 g0 = ((const float4*)gamma)[lane];
    float4 g1 = ((const float4*)gamma)[lane + 32];
    float4 b0 = ((const float4*)beta)[lane];
    float4 b1 = ((const float4*)beta)[lane + 32];

    float4 o0, o1;
    o0.x = (v0.x - mu) * inv * g0.x + b0.x;
    o0.y = (v0.y - mu) * inv * g0.y + b0.y;
    o0.z = (v0.z - mu) * inv * g0.z + b0.z;
    o0.w = (v0.w - mu) * inv * g0.w + b0.w;
    o1.x = (v1.x - mu) * inv * g1.x + b1.x;
    o1.y = (v1.y - mu) * inv * g1.y + b1.y;
    o1.z = (v1.z - mu) * inv * g1.z + b1.z;
    o1.w = (v1.w - mu) * inv * g1.w + b1.w;

    uint2* orow = (uint2*)(out + (size_t)gw * 256);
    orow[lane]      = pack4_bf16(o0);
    orow[lane + 32] = pack4_bf16(o1);
}

// ---------------------------------------------------------------------------
// bf16 tensor-core GEMM, BK=64, 3-stage pipeline + register fragment
// double-buffering (R9/R11 champion mainloop; grid n-major).
// ---------------------------------------------------------------------------
#define EPI_BIAS 0
#define EPI_GELU 1
#define EPI_MLP2 3

#define AS 72
#define BSS 136
#define A_STG (128 * AS)
#define B_STG (64 * BSS)
#define GEMM_SMEM ((3 * A_STG + 3 * B_STG) * 2)   // 107520 bytes

template <int EPI, bool OUT_BF16>
__global__ void __launch_bounds__(256, 2) gemm_bf16(const __nv_bfloat16* __restrict__ A,
                                                    const __nv_bfloat16* __restrict__ B,
                                                    const float* __restrict__ bias,
                                                    void* __restrict__ Cout,
                                                    const float* __restrict__ res,
                                                    int N, int K) {
    extern __shared__ __align__(16) __nv_bfloat16 smp[];
    __nv_bfloat16* Asm = smp;
    __nv_bfloat16* Bsm = smp + 3 * A_STG;

    const int tid  = threadIdx.x;
    const int lane = tid & 31;
    const int wid  = tid >> 5;
    const int bm   = blockIdx.y * 128;
    const int bn   = blockIdx.x * 128;
    const int wm   = (wid & 3) * 32;
    const int wn   = (wid >> 2) * 64;

    const __nv_bfloat16* Ab = A + (size_t)bm * K;
    const __nv_bfloat16* Bb = B + bn;

    float acc[2][8][4] = {};

    auto load_tile = [&](int k0, int stg) {
        __nv_bfloat16* as = Asm + stg * A_STG;
        __nv_bfloat16* bs = Bsm + stg * B_STG;
#pragma unroll
        for (int i = 0; i < 4; i++) {
            int c = tid + i * 256;
            int row = c >> 3, kc = (c & 7) * 8;
            cpasync16(&as[row * AS + kc], Ab + (size_t)row * K + k0 + kc);
        }
#pragma unroll
        for (int i = 0; i < 4; i++) {
            int c = tid + i * 256;
            int k = c >> 4, n = (c & 15) * 8;
            cpasync16(&bs[k * BSS + n], Bb + (size_t)(k0 + k) * N + n);
        }
        cp_commit();
    };

    const int nIter = K >> 6;
    load_tile(0, 0);
    load_tile(64, 1);

    const int aoff0 = (wm + (lane & 15)) * AS + (lane >> 4) * 8;
    const int aoff1 = aoff0 + 16 * AS;
    const int boff  = ((lane & 7) + ((lane >> 3) & 1) * 8) * BSS
                      + wn + (lane >> 4) * 8;

    for (int i = 0; i < nIter; i++) {
        if (i + 1 < nIter) cp_wait<1>(); else cp_wait<0>();
        __syncthreads();
        if (i + 2 < nIter) load_tile((i + 2) * 64, (i + 2) % 3);

        const __nv_bfloat16* as = Asm + (i % 3) * A_STG;
        const __nv_bfloat16* bs = Bsm + (i % 3) * B_STG;
        const __nv_bfloat16* a0 = as + aoff0;
        const __nv_bfloat16* a1 = as + aoff1;
        const __nv_bfloat16* bp = bs + boff;

        uint32_t af[2][2][4];
        uint32_t bf[2][4];
        ldsm4(af[0][0], a0);
        ldsm4(af[0][1], a1);
        ldsm4t(bf[0], bp);
#pragma unroll
        for (int s = 0; s < 16; s++) {
            const int ks = (s >> 2) * 16;
            const int np = s & 3;
            const int ca = (s >> 2) & 1;
            const int cb = s & 1;
            if (np == 2 && ks < 48) {
                ldsm4(af[ca ^ 1][0], a0 + ks + 16);
                ldsm4(af[ca ^ 1][1], a1 + ks + 16);
            }
            if (s < 15) {
                const int ns = s + 1;
                ldsm4t(bf[cb ^ 1], bp + ((ns >> 2) * 16) * BSS + (ns & 3) * 16);
            }
            mma_bf16(acc[0][np * 2 + 0], af[ca][0], bf[cb][0], bf[cb][1]);
            mma_bf16(acc[1][np * 2 + 0], af[ca][1], bf[cb][0], bf[cb][1]);
            mma_bf16(acc[0][np * 2 + 1], af[ca][0], bf[cb][2], bf[cb][3]);
            mma_bf16(acc[1][np * 2 + 1], af[ca][1], bf[cb][2], bf[cb][3]);
        }
    }

    // ---------------- epilogue ----------------
    float bv0[8], bv1[8];
#pragma unroll
    for (int ni = 0; ni < 8; ni++) {
        int c = bn + wn + ni * 8 + 2 * (lane & 3);
        bv0[ni] = bias[c];
        bv1[ni] = bias[c + 1];
    }

#pragma unroll
    for (int mi = 0; mi < 2; mi++) {
#pragma unroll
        for (int half = 0; half < 2; half++) {
            int r = bm + wm + mi * 16 + (lane >> 2) + half * 8;
            size_t rowoff = (size_t)r * N;
#pragma unroll
            for (int ni = 0; ni < 8; ni++) {
                int c = bn + wn + ni * 8 + 2 * (lane & 3);
                float v0 = acc[mi][ni][half * 2 + 0] + bv0[ni];
                float v1 = acc[mi][ni][half * 2 + 1] + bv1[ni];
                if (EPI == EPI_GELU) { v0 = gelu_tanh(v0); v1 = gelu_tanh(v1); }
                if (EPI == EPI_MLP2) {
                    float2 rr = *(const float2*)(res + rowoff + c);
                    v0 += rr.x; v1 += rr.y;
                }
                if (OUT_BF16) {
                    __nv_bfloat162 w = __floats2bfloat162_rn(v0, v1);
                    *(__nv_bfloat162*)((__nv_bfloat16*)Cout + rowoff + c) = w;
                } else {
                    float2 w = {v0, v1};
                    *(float2*)((float*)Cout + rowoff + c) = w;
                }
            }
        }
    }
}

// ---------------------------------------------------------------------------
// PROJ + residual + LN2 fused GEMM (unchanged).
// ---------------------------------------------------------------------------
#define PS_AS 40
#define PS_BS 264
#define PS_A_STG (64 * PS_AS)
#define PS_B_STG (32 * PS_BS)
#define PROJ_SMEM ((4 * PS_A_STG + 4 * PS_B_STG) * 2)   // 88064

__global__ void __launch_bounds__(256, 2) gemm_proj_ln(
    const __nv_bfloat16* __restrict__ A,
    const __nv_bfloat16* __restrict__ B,
    const float* __restrict__ bias,
    const float* __restrict__ xres,
    const float* __restrict__ gamma,
    const float* __restrict__ beta,
    float* __restrict__ x1,
    __nv_bfloat16* __restrict__ h2) {
    extern __shared__ __align__(16) __nv_bfloat16 smp[];
    __nv_bfloat16* Asm = smp;
    __nv_bfloat16* Bsm = smp + 4 * PS_A_STG;

    const int tid  = threadIdx.x;
    const int lane = tid & 31;
    const int wid  = tid >> 5;
    const int bm   = blockIdx.x * 64;
    const int wm   = (wid & 1) * 32;
    const int wn   = (wid >> 1) * 64;
    const int K = 256, N = 256;

    const __nv_bfloat16* Ab = A + (size_t)bm * K;

    float acc[2][8][4] = {};

    auto load_tile = [&](int k0, int stg) {
        __nv_bfloat16* as = Asm + stg * PS_A_STG;
        __nv_bfloat16* bs = Bsm + stg * PS_B_STG;
        {
            int row = tid >> 2, kc = (tid & 3) * 8;
            cpasync16(&as[row * PS_AS + kc], Ab + (size_t)row * K + k0 + kc);
        }
#pragma unroll
        for (int i = 0; i < 4; i++) {
            int c = tid + i * 256;
            int k = c >> 5, n = (c & 31) * 8;
            cpasync16(&bs[k * PS_BS + n], B + (size_t)(k0 + k) * N + n);
        }
        cp_commit();
    };

    const int nIter = 8;
    load_tile(0, 0);
    load_tile(32, 1);
    load_tile(64, 2);

    for (int i = 0; i < nIter; i++) {
        if      (i + 2 < nIter) cp_wait<2>();
        else if (i + 1 < nIter) cp_wait<1>();
        else                    cp_wait<0>();
        __syncthreads();
        if (i + 3 < nIter) load_tile((i + 3) * 32, (i + 3) & 3);

        const __nv_bfloat16* as = Asm + (i & 3) * PS_A_STG;
        const __nv_bfloat16* bs = Bsm + (i & 3) * PS_B_STG;
#pragma unroll
        for (int ks = 0; ks < 32; ks += 16) {
            uint32_t af[2][4];
#pragma unroll
            for (int mi = 0; mi < 2; mi++)
                ldsm4(af[mi], as + (wm + mi * 16 + (lane & 15)) * PS_AS
                                 + ks + (lane >> 4) * 8);
#pragma unroll
            for (int np = 0; np < 4; np++) {
                uint32_t bf[4];
                ldsm4t(bf, bs + (ks + (lane & 7) + ((lane >> 3) & 1) * 8) * PS_BS
                              + wn + np * 16 + (lane >> 4) * 8);
                mma_bf16(acc[0][np * 2 + 0], af[0], bf[0], bf[1]);
                mma_bf16(acc[1][np * 2 + 0], af[1], bf[0], bf[1]);
                mma_bf16(acc[0][np * 2 + 1], af[0], bf[2], bf[3]);
                mma_bf16(acc[1][np * 2 + 1], af[1], bf[2], bf[3]);
            }
        }
    }
    __syncthreads();

    // x1 = acc + bias + x, staged in smem
    float* x1s = (float*)smp;
    const int S = 264;

    float bv0[8], bv1[8];
#pragma unroll
    for (int ni = 0; ni < 8; ni++) {
        int c = wn + ni * 8 + 2 * (lane & 3);
        bv0[ni] = bias[c];
        bv1[ni] = bias[c + 1];
    }

#pragma unroll
    for (int mi = 0; mi < 2; mi++) {
#pragma unroll
        for (int half = 0; half < 2; half++) {
            int row  = wm + mi * 16 + (lane >> 2) + half * 8;
            int xrow = win_to_x_row(bm + row);
            size_t off = (size_t)xrow * 256;
#pragma unroll
            for (int ni = 0; ni < 8; ni++) {
                int c = wn + ni * 8 + 2 * (lane & 3);
                float v0 = acc[mi][ni][half * 2 + 0] + bv0[ni];
                float v1 = acc[mi][ni][half * 2 + 1] + bv1[ni];
                float2 rr = *(const float2*)(xres + off + c);
                v0 += rr.x; v1 += rr.y;
                float2 w = {v0, v1};
                *(float2*)(x1 + off + c)      = w;
                *(float2*)(&x1s[row * S + c]) = w;
            }
        }
    }
    __syncthreads();

    // in-block LN2
    float4 g0 = *(const float4*)(gamma + lane * 8);
    float4 g1 = *(const float4*)(gamma + lane * 8 + 4);
    float4 be0 = *(const float4*)(beta + lane * 8);
    float4 be1 = *(const float4*)(beta + lane * 8 + 4);

#pragma unroll
    for (int rr = 0; rr < 8; rr++) {
        int row = wid * 8 + rr;
        float4 u0 = *(const float4*)(&x1s[row * S + lane * 8]);
        float4 u1 = *(const float4*)(&x1s[row * S + lane * 8 + 4]);

        float s  = u0.x + u0.y + u0.z + u0.w + u1.x + u1.y + u1.z + u1.w;
        float ss = u0.x*u0.x + u0.y*u0.y + u0.z*u0.z + u0.w*u0.w
                 + u1.x*u1.x + u1.y*u1.y + u1.z*u1.z + u1.w*u1.w;
#pragma unroll
        for (int o = 16; o; o >>= 1) {
            s  += __shfl_xor_sync(0xffffffffu, s,  o);
            ss += __shfl_xor_sync(0xffffffffu, ss, o);
        }
        float mu  = s * (1.0f / 256.0f);
        float inv = rsqrtf(ss * (1.0f / 256.0f) - mu * mu + 1e-5f);

        float4 o0, o1;
        o0.x = (u0.x - mu) * inv * g0.x + be0.x;
        o0.y = (u0.y - mu) * inv * g0.y + be0.y;
        o0.z = (u0.z - mu) * inv * g0.z + be0.z;
        o0.w = (u0.w - mu) * inv * g0.w + be0.w;
        o1.x = (u1.x - mu) * inv * g1.x + be1.x;
        o1.y = (u1.y - mu) * inv * g1.y + be1.y;
        o1.z = (u1.z - mu) * inv * g1.z + be1.z;
        o1.w = (u1.w - mu) * inv * g1.w + be1.w;

        int xrow = win_to_x_row(bm + row);
        uint2 p0 = pack4_bf16(o0);
        uint2 p1 = pack4_bf16(o1);
        uint4 pk = make_uint4(p0.x, p0.y, p1.x, p1.y);
        *(uint4*)(h2 + (size_t)xrow * 256 + lane * 8) = pk;
    }
}

// ---------------------------------------------------------------------------
// Tensor-core windowed attention, softmax cost reduced:
//  - bias table prescaled by log2e; SCALE and mask folded -> raw ex2.approx
//  - sInfo read as int2 pairs (halved LDS)
//  - split accumulators break the exp->add dependency chain
// ---------------------------------------------------------------------------
#define ATS 40

__global__ void __launch_bounds__(64) attn_tc(const __nv_bfloat16* __restrict__ qkv,
                                              const float* __restrict__ bias_table,
                                              __nv_bfloat16* __restrict__ out) {
    __shared__ __align__(16) __nv_bfloat16 sK[2][64 * ATS];
    __shared__ __align__(16) __nv_bfloat16 sV[2][64 * ATS];
    __shared__ float sB[2][169];
    __shared__ int   sInfo[64];

    const int w     = blockIdx.x >> 2;
    const int wp    = threadIdx.x >> 5;
    const int lane  = threadIdx.x & 31;
    const int h     = (blockIdx.x & 3) * 2 + wp;
    const int wbase = w * 49;
    const int wi    = w & 63;

    if (threadIdx.x < 64) {
        int j = threadIdx.x;
        int info;
        if (j < 49) {
            int rj = j / 7, cj = j - (j / 7) * 7;
            int gr = (wi >> 3) * 7 + rj;
            int gc = (wi & 7) * 7 + cj;
            int rh = (gr < 49) ? 0 : ((gr < 53) ? 1 : 2);
            int rc = (gc < 49) ? 0 : ((gc < 53) ? 1 : 2);
            int key = rj + 13 * cj;
            info = key | ((rh * 3 + rc) << 8) | (1 << 16);
        } else {
            info = 0 | (255 << 8);
        }
        sInfo[j] = info;
    }

    // bias prescaled by log2(e) for raw ex2
    for (int idx = lane; idx < 169; idx += 32)
        sB[wp][idx] = bias_table[idx * 8 + h] * LOG2E;

    for (int tsk = lane; tsk < 196; tsk += 32) {
        int row = tsk >> 2, seg = (tsk & 3) * 8;
        const __nv_bfloat16* base = qkv + (size_t)(wbase + row) * 768 + h * 32 + seg;
        int off = row * ATS + seg;
        *(uint4*)&sK[wp][off] = *(const uint4*)(base + 256);
        *(uint4*)&sV[wp][off] = *(const uint4*)(base + 512);
    }
    for (int z = lane; z < 60; z += 32) {
        int row = 49 + (z >> 2), seg = (z & 3) * 8;
        int off = row * ATS + seg;
        uint4 zz = make_uint4(0, 0, 0, 0);
        *(uint4*)&sK[wp][off] = zz;
        *(uint4*)&sV[wp][off] = zz;
    }
    __syncthreads();

    const int q2 = 2 * (lane & 3);
    const int r = lane >> 2;
    const __nv_bfloat16* qb = qkv + (size_t)wbase * 768 + h * 32;

#pragma unroll
    for (int mt = 0; mt < 4; mt++) {
        const int r0 = mt * 16 + r;
        const int r1 = r0 + 8;
        const bool v0 = (r0 < 49), v1 = (r1 < 49);
        uint32_t qf[2][4];
#pragma unroll
        for (int ks = 0; ks < 2; ks++) {
            const int cc = q2 + ks * 16;
            qf[ks][0] = v0 ? *(const uint32_t*)(qb + (size_t)r0 * 768 + cc)     : 0u;
            qf[ks][1] = v1 ? *(const uint32_t*)(qb + (size_t)r1 * 768 + cc)     : 0u;
            qf[ks][2] = v0 ? *(const uint32_t*)(qb + (size_t)r0 * 768 + cc + 8) : 0u;
            qf[ks][3] = v1 ? *(const uint32_t*)(qb + (size_t)r1 * 768 + cc + 8) : 0u;
        }

        float c[8][4] = {};
#pragma unroll
        for (int nt = 0; nt < 4; nt++) {
#pragma unroll
            for (int ks = 0; ks < 2; ks++) {
                uint32_t kf[4];
                ldsm4(kf, &sK[wp][(nt * 16 + (lane & 7) + ((lane >> 4) & 1) * 8) * ATS
                                  + ks * 16 + ((lane >> 3) & 1) * 8]);
                mma_bf16(c[2 * nt + 0], qf[ks], kf[0], kf[1]);
                mma_bf16(c[2 * nt + 1], qf[ks], kf[2], kf[3]);
            }
        }

        int infLo = sInfo[r0 < 64 ? r0 : 0], infHi = sInfo[r1 < 64 ? r1 : 0];
        int keyLo = (infLo & 255) + 84, regLo = (infLo >> 8) & 255;
        int keyHi = (infHi & 255) + 84, regHi = (infHi >> 8) & 255;

        float s0 = 0.0f, s1 = 0.0f, t0 = 0.0f, t1 = 0.0f;
#pragma unroll
        for (int u = 0; u < 8; u++) {
            int2 ii = *(const int2*)&sInfo[u * 8 + q2];
#pragma unroll
            for (int e = 0; e < 2; e++) {
                int inf = e ? ii.y : ii.x;
                float pLo, pHi;
                if (inf & 0x10000) {
                    int kj = inf & 255;
                    int rj = (inf >> 8) & 255;
                    float aLo = fmaf(c[u][e],     SCALE_Q_L2E, sB[wp][keyLo - kj]);
                    float aHi = fmaf(c[u][2 + e], SCALE_Q_L2E, sB[wp][keyHi - kj]);
                    if (rj != regLo) aLo -= MASK_L2E;
                    if (rj != regHi) aHi -= MASK_L2E;
                    pLo = ex2f(aLo);
                    pHi = ex2f(aHi);
                } else {
                    pLo = 0.0f; pHi = 0.0f;
                }
                c[u][e]     = pLo;
                c[u][2 + e] = pHi;
                if (e) { s1 += pLo; t1 += pHi; }
                else   { s0 += pLo; t0 += pHi; }
            }
        }
        float sumLo = s0 + s1;
        float sumHi = t0 + t1;
        sumLo += __shfl_xor_sync(0xffffffffu, sumLo, 1);
        sumLo += __shfl_xor_sync(0xffffffffu, sumLo, 2);
        sumHi += __shfl_xor_sync(0xffffffffu, sumHi, 1);
        sumHi += __shfl_xor_sync(0xffffffffu, sumHi, 2);
        float dLo = 1.0f / sumLo;
        float dHi = 1.0f / sumHi;

        uint32_t pa[4][4];
#pragma unroll
        for (int t = 0; t < 4; t++) {
            pa[t][0] = pack2_bf16(c[2 * t][0] * dLo,     c[2 * t][1] * dLo);
            pa[t][1] = pack2_bf16(c[2 * t][2] * dHi,     c[2 * t][3] * dHi);
            pa[t][2] = pack2_bf16(c[2 * t + 1][0] * dLo, c[2 * t + 1][1] * dLo);
            pa[t][3] = pack2_bf16(c[2 * t + 1][2] * dHi, c[2 * t + 1][3] * dHi);
        }

        float o[4][4] = {};
#pragma unroll
        for (int ks = 0; ks < 4; ks++) {
            uint32_t vf[2][4];
#pragma unroll
            for (int half = 0; half < 2; half++)
                ldsm4t(vf[half], &sV[wp][(ks * 16 + (lane & 7) + ((lane >> 3) & 1) * 8) * ATS
                                         + half * 16 + (lane >> 4) * 8]);
            mma_bf16(o[0], pa[ks], vf[0][0], vf[0][1]);
            mma_bf16(o[1], pa[ks], vf[0][2], vf[0][3]);
            mma_bf16(o[2], pa[ks], vf[1][0], vf[1][1]);
            mma_bf16(o[3], pa[ks], vf[1][2], vf[1][3]);
        }

        if (r0 < 49) {
            __nv_bfloat16* p = out + (size_t)(wbase + r0) * 256 + h * 32 + q2;
#pragma unroll
            for (int on = 0; on < 4; on++)
                *(uint32_t*)(p + on * 8) = pack2_bf16(o[on][0], o[on][1]);
        }
        if (r1 < 49) {
            __nv_bfloat16* p = out + (size_t)(wbase + r1) * 256 + h * 32 + q2;
#pragma unroll
            for (int on = 0; on < 4; on++)
                *(uint32_t*)(p + on * 8) = pack2_bf16(o[on][2], o[on][3]);
        }
    }
}

// ---------------------------------------------------------------------------
// Host launcher (graph-capturable: kernel launches only)
// ---------------------------------------------------------------------------
extern "C" void kernel_launch(void* const* d_in, const int* in_sizes, int n_in,
                              void* d_out, int out_size) {
    (void)in_sizes; (void)n_in; (void)out_size;

    const float* x          = (const float*)d_in[0];
    const float* n1g        = (const float*)d_in[1];
    const float* n1b        = (const float*)d_in[2];
    const float* qkv_w      = (const float*)d_in[3];
    const float* qkv_b      = (const float*)d_in[4];
    const float* proj_w     = (const float*)d_in[5];
    const float* proj_b     = (const float*)d_in[6];
    const float* bias_table = (const float*)d_in[7];
    const float* n2g        = (const float*)d_in[8];
    const float* n2b        = (const float*)d_in[9];
    const float* w1         = (const float*)d_in[10];
    const float* b1         = (const float*)d_in[11];
    const float* w2         = (const float*)d_in[12];
    const float* b2         = (const float*)d_in[13];
    float* out = (float*)d_out;

    __nv_bfloat16 *ywin, *qkvb, *attnb, *h2, *act, *wbf;
    float *x1;
    cudaGetSymbolAddress((void**)&ywin,  g_ywin);
    cudaGetSymbolAddress((void**)&qkvb,  g_qkv);
    cudaGetSymbolAddress((void**)&attnb, g_attn);
    cudaGetSymbolAddress((void**)&x1,    g_x1);
    cudaGetSymbolAddress((void**)&h2,    g_h2);
    cudaGetSymbolAddress((void**)&act,   g_act);
    cudaGetSymbolAddress((void**)&wbf,   g_wbf);

    cudaFuncSetAttribute(gemm_bf16<EPI_BIAS, true>,
                         cudaFuncAttributeMaxDynamicSharedMemorySize, GEMM_SMEM);
    cudaFuncSetAttribute(gemm_bf16<EPI_GELU, true>,
                         cudaFuncAttributeMaxDynamicSharedMemorySize, GEMM_SMEM);
    cudaFuncSetAttribute(gemm_bf16<EPI_MLP2, false>,
                         cudaFuncAttributeMaxDynamicSharedMemorySize, GEMM_SMEM);
    cudaFuncSetAttribute(gemm_proj_ln,
                         cudaFuncAttributeMaxDynamicSharedMemorySize, PROJ_SMEM);

    const int lnBlocks = NROWS / 8;

    // 0) weights -> bf16
    wconv_kernel<<<768, 1024>>>(qkv_w, proj_w, w1, w2, wbf);
    // 1) LN1 + cyclic shift + window partition -> bf16
    ln_kernel<<<lnBlocks, 256>>>(x, n1g, n1b, ywin);
    // 2) QKV: [100352,256] @ [256,768] -> bf16
    gemm_bf16<EPI_BIAS, true><<<dim3(6, 784), 256, GEMM_SMEM>>>(ywin, wbf + WOFF_QKV,
                                                                qkv_b, qkvb, nullptr, 768, 256);
    // 3) windowed attention (tensor cores) -> bf16
    attn_tc<<<NWIN * 4, 64>>>(qkvb, bias_table, attnb);
    // 4) proj + window-reverse + un-shift + residual + LN2 (fused) -> x1, h2
    gemm_proj_ln<<<1568, 256, PROJ_SMEM>>>(attnb, wbf + WOFF_PROJ, proj_b,
                                           x, n2g, n2b, x1, h2);
    // 5) MLP up + GELU: [100352,256] @ [256,1024] -> bf16
    gemm_bf16<EPI_GELU, true><<<dim3(8, 784), 256, GEMM_SMEM>>>(h2, wbf + WOFF_W1,
                                                                b1, act, nullptr, 1024, 256);
    // 6) MLP down + residual -> d_out (fp32): [100352,1024] @ [1024,256]
    gemm_bf16<EPI_MLP2, false><<<dim3(2, 784), 256, GEMM_SMEM>>>(act, wbf + WOFF_W2,
                                                                 b2, out, x1, 256, 1024);
}

// round 16
// speedup vs baseline: 1.1843x; 1.0102x over previous
#include <cuda_runtime.h>
#include <cuda_bf16.h>
#include <cstddef>
#include <cstdint>

// ---------------------------------------------------------------------------
// Problem constants
// ---------------------------------------------------------------------------
#define NROWS   100352            // 32 * 56 * 56 tokens
#define NWIN    2048              // 32 * 64 windows
#define SCALE_Q 0.17677669529663689f   // 32^-0.5
#define LOG2E   1.4426950408889634f
#define SCALE_Q_L2E (SCALE_Q * LOG2E)
#define MASK_L2E 144.26950408889634f   // 100 * log2(e)

// ---------------------------------------------------------------------------
// Scratch (static __device__ arrays; allocation is forbidden)
// ---------------------------------------------------------------------------
__device__ __align__(16) __nv_bfloat16 g_ywin[100352 * 256];   // LN1 out (win order)
__device__ __align__(16) __nv_bfloat16 g_qkv [100352 * 768];   // qkv, bf16
__device__ __align__(16) __nv_bfloat16 g_attn[100352 * 256];   // attention out
__device__ float                       g_x1  [100352 * 256];   // shortcut + proj
__device__ __align__(16) __nv_bfloat16 g_h2  [100352 * 256];   // LN2 out
__device__ __align__(16) __nv_bfloat16 g_act [100352 * 1024];  // gelu(mlp1)
__device__ __align__(16) __nv_bfloat16 g_wbf [786432];         // all 4 weights, bf16

#define WOFF_QKV  0
#define WOFF_PROJ 196608
#define WOFF_W1   262144
#define WOFF_W2   524288

// ---------------------------------------------------------------------------
// window-order row <-> x-order row mapping (shift = 3, 8x8 windows of 7x7)
// ---------------------------------------------------------------------------
__device__ __forceinline__ int win_to_x_row(int m) {
    int w  = m / 49;
    int t  = m - w * 49;
    int b  = w >> 6;
    int wi = w & 63;
    int tr = t / 7;
    int tc = t - tr * 7;
    int gr = ((wi >> 3) * 7) + tr;
    int gc = ((wi & 7) * 7) + tc;
    int r = gr + 3; if (r >= 56) r -= 56;
    int c = gc + 3; if (c >= 56) c -= 56;
    return b * 3136 + r * 56 + c;
}

__device__ __forceinline__ float gelu_tanh(float x) {
    float x3 = x * x * x;
    return 0.5f * x * (1.0f + tanhf(0.7978845608028654f * (x + 0.044715f * x3)));
}

__device__ __forceinline__ uint2 pack4_bf16(float4 v) {
    __nv_bfloat162 lo = __floats2bfloat162_rn(v.x, v.y);
    __nv_bfloat162 hi = __floats2bfloat162_rn(v.z, v.w);
    uint2 r;
    r.x = *(uint32_t*)&lo;
    r.y = *(uint32_t*)&hi;
    return r;
}

__device__ __forceinline__ uint32_t pack2_bf16(float a, float b) {
    __nv_bfloat162 t = __floats2bfloat162_rn(a, b);
    return *(uint32_t*)&t;
}

__device__ __forceinline__ float ex2f(float x) {
    float y;
    asm("ex2.approx.f32 %0, %1;" : "=f"(y) : "f"(x));
    return y;
}

// ---------------------------------------------------------------------------
// PTX helpers
// ---------------------------------------------------------------------------
__device__ __forceinline__ void ldsm4(uint32_t r[4], const void* p) {
    uint32_t a = (uint32_t)__cvta_generic_to_shared(p);
    asm("ldmatrix.sync.aligned.m8n8.x4.shared.b16 {%0,%1,%2,%3}, [%4];"
        : "=r"(r[0]), "=r"(r[1]), "=r"(r[2]), "=r"(r[3]) : "r"(a) : "memory");
}
__device__ __forceinline__ void ldsm4t(uint32_t r[4], const void* p) {
    uint32_t a = (uint32_t)__cvta_generic_to_shared(p);
    asm("ldmatrix.sync.aligned.m8n8.x4.trans.shared.b16 {%0,%1,%2,%3}, [%4];"
        : "=r"(r[0]), "=r"(r[1]), "=r"(r[2]), "=r"(r[3]) : "r"(a) : "memory");
}
__device__ __forceinline__ void mma_bf16(float c[4], const uint32_t a[4],
                                         uint32_t b0, uint32_t b1) {
    asm("mma.sync.aligned.m16n8k16.row.col.f32.bf16.bf16.f32 "
        "{%0,%1,%2,%3}, {%4,%5,%6,%7}, {%8,%9}, {%0,%1,%2,%3};"
        : "+f"(c[0]), "+f"(c[1]), "+f"(c[2]), "+f"(c[3])
        : "r"(a[0]), "r"(a[1]), "r"(a[2]), "r"(a[3]), "r"(b0), "r"(b1));
}
__device__ __forceinline__ void cpasync16(void* dst, const void* src) {
    uint32_t d = (uint32_t)__cvta_generic_to_shared(dst);
    asm volatile("cp.async.cg.shared.global [%0], [%1], 16;" :: "r"(d), "l"(src));
}
__device__ __forceinline__ void cp_commit() {
    asm volatile("cp.async.commit_group;");
}
template <int N>
__device__ __forceinline__ void cp_wait() {
    asm volatile("cp.async.wait_group %0;" :: "n"(N));
}

// ---------------------------------------------------------------------------
// Weight conversion: fp32 -> bf16, once per launch
// ---------------------------------------------------------------------------
__global__ void __launch_bounds__(1024) wconv_kernel(const float* __restrict__ qkv_w,
                                                     const float* __restrict__ proj_w,
                                                     const float* __restrict__ w1,
                                                     const float* __restrict__ w2,
                                                     __nv_bfloat16* __restrict__ dst) {
    int i = blockIdx.x * 1024 + threadIdx.x;   // grid = 768
    float v;
    if      (i < WOFF_PROJ) v = qkv_w[i];
    else if (i < WOFF_W1)   v = proj_w[i - WOFF_PROJ];
    else if (i < WOFF_W2)   v = w1[i - WOFF_W1];
    else                    v = w2[i - WOFF_W2];
    dst[i] = __float2bfloat16(v);
}

// ---------------------------------------------------------------------------
// LayerNorm (LN1 only): one warp per 256-wide row, gather + bf16 output.
// ---------------------------------------------------------------------------
__global__ void __launch_bounds__(256) ln_kernel(const float* __restrict__ in,
                                                 const float* __restrict__ gamma,
                                                 const float* __restrict__ beta,
                                                 __nv_bfloat16* __restrict__ out) {
    int gw   = (blockIdx.x * blockDim.x + threadIdx.x) >> 5;
    int lane = threadIdx.x & 31;
    if (gw >= NROWS) return;
    int src = win_to_x_row(gw);

    const float4* row = (const float4*)(in + (size_t)src * 256);
    float4 v0 = row[lane];
    float4 v1 = row[lane + 32];

    float s  = v0.x + v0.y + v0.z + v0.w + v1.x + v1.y + v1.z + v1.w;
    float ss = v0.x*v0.x + v0.y*v0.y + v0.z*v0.z + v0.w*v0.w
             + v1.x*v1.x + v1.y*v1.y + v1.z*v1.z + v1.w*v1.w;
#pragma unroll
    for (int o = 16; o; o >>= 1) {
        s  += __shfl_xor_sync(0xffffffffu, s,  o);
        ss += __shfl_xor_sync(0xffffffffu, ss, o);
    }
    float mu  = s * (1.0f / 256.0f);
    float inv = rsqrtf(ss * (1.0f / 256.0f) - mu * mu + 1e-5f);

    float4 g0 = ((const float4*)gamma)[lane];
    float4 g1 = ((const float4*)gamma)[lane + 32];
    float4 b0 = ((const float4*)beta)[lane];
    float4 b1 = ((const float4*)beta)[lane + 32];

    float4 o0, o1;
    o0.x = (v0.x - mu) * inv * g0.x + b0.x;
    o0.y = (v0.y - mu) * inv * g0.y + b0.y;
    o0.z = (v0.z - mu) * inv * g0.z + b0.z;
    o0.w = (v0.w - mu) * inv * g0.w + b0.w;
    o1.x = (v1.x - mu) * inv * g1.x + b1.x;
    o1.y = (v1.y - mu) * inv * g1.y + b1.y;
    o1.z = (v1.z - mu) * inv * g1.z + b1.z;
    o1.w = (v1.w - mu) * inv * g1.w + b1.w;

    uint2* orow = (uint2*)(out + (size_t)gw * 256);
    orow[lane]      = pack4_bf16(o0);
    orow[lane + 32] = pack4_bf16(o1);
}

// ---------------------------------------------------------------------------
// bf16 tensor-core GEMM, BK=64, 3-stage pipeline + register fragment
// double-buffering (champion mainloop; at the mma.sync HW ceiling).
// ---------------------------------------------------------------------------
#define EPI_BIAS 0
#define EPI_GELU 1
#define EPI_MLP2 3

#define AS 72
#define BSS 136
#define A_STG (128 * AS)
#define B_STG (64 * BSS)
#define GEMM_SMEM ((3 * A_STG + 3 * B_STG) * 2)   // 107520 bytes

template <int EPI, bool OUT_BF16>
__global__ void __launch_bounds__(256, 2) gemm_bf16(const __nv_bfloat16* __restrict__ A,
                                                    const __nv_bfloat16* __restrict__ B,
                                                    const float* __restrict__ bias,
                                                    void* __restrict__ Cout,
                                                    const float* __restrict__ res,
                                                    int N, int K) {
    extern __shared__ __align__(16) __nv_bfloat16 smp[];
    __nv_bfloat16* Asm = smp;
    __nv_bfloat16* Bsm = smp + 3 * A_STG;

    const int tid  = threadIdx.x;
    const int lane = tid & 31;
    const int wid  = tid >> 5;
    const int bm   = blockIdx.y * 128;
    const int bn   = blockIdx.x * 128;
    const int wm   = (wid & 3) * 32;
    const int wn   = (wid >> 2) * 64;

    const __nv_bfloat16* Ab = A + (size_t)bm * K;
    const __nv_bfloat16* Bb = B + bn;

    float acc[2][8][4] = {};

    auto load_tile = [&](int k0, int stg) {
        __nv_bfloat16* as = Asm + stg * A_STG;
        __nv_bfloat16* bs = Bsm + stg * B_STG;
#pragma unroll
        for (int i = 0; i < 4; i++) {
            int c = tid + i * 256;
            int row = c >> 3, kc = (c & 7) * 8;
            cpasync16(&as[row * AS + kc], Ab + (size_t)row * K + k0 + kc);
        }
#pragma unroll
        for (int i = 0; i < 4; i++) {
            int c = tid + i * 256;
            int k = c >> 4, n = (c & 15) * 8;
            cpasync16(&bs[k * BSS + n], Bb + (size_t)(k0 + k) * N + n);
        }
        cp_commit();
    };

    const int nIter = K >> 6;
    load_tile(0, 0);
    load_tile(64, 1);

    const int aoff0 = (wm + (lane & 15)) * AS + (lane >> 4) * 8;
    const int aoff1 = aoff0 + 16 * AS;
    const int boff  = ((lane & 7) + ((lane >> 3) & 1) * 8) * BSS
                      + wn + (lane >> 4) * 8;

    for (int i = 0; i < nIter; i++) {
        if (i + 1 < nIter) cp_wait<1>(); else cp_wait<0>();
        __syncthreads();
        if (i + 2 < nIter) load_tile((i + 2) * 64, (i + 2) % 3);

        const __nv_bfloat16* as = Asm + (i % 3) * A_STG;
        const __nv_bfloat16* bs = Bsm + (i % 3) * B_STG;
        const __nv_bfloat16* a0 = as + aoff0;
        const __nv_bfloat16* a1 = as + aoff1;
        const __nv_bfloat16* bp = bs + boff;

        uint32_t af[2][2][4];
        uint32_t bf[2][4];
        ldsm4(af[0][0], a0);
        ldsm4(af[0][1], a1);
        ldsm4t(bf[0], bp);
#pragma unroll
        for (int s = 0; s < 16; s++) {
            const int ks = (s >> 2) * 16;
            const int np = s & 3;
            const int ca = (s >> 2) & 1;
            const int cb = s & 1;
            if (np == 2 && ks < 48) {
                ldsm4(af[ca ^ 1][0], a0 + ks + 16);
                ldsm4(af[ca ^ 1][1], a1 + ks + 16);
            }
            if (s < 15) {
                const int ns = s + 1;
                ldsm4t(bf[cb ^ 1], bp + ((ns >> 2) * 16) * BSS + (ns & 3) * 16);
            }
            mma_bf16(acc[0][np * 2 + 0], af[ca][0], bf[cb][0], bf[cb][1]);
            mma_bf16(acc[1][np * 2 + 0], af[ca][1], bf[cb][0], bf[cb][1]);
            mma_bf16(acc[0][np * 2 + 1], af[ca][0], bf[cb][2], bf[cb][3]);
            mma_bf16(acc[1][np * 2 + 1], af[ca][1], bf[cb][2], bf[cb][3]);
        }
    }

    // ---------------- epilogue ----------------
    float bv0[8], bv1[8];
#pragma unroll
    for (int ni = 0; ni < 8; ni++) {
        int c = bn + wn + ni * 8 + 2 * (lane & 3);
        bv0[ni] = bias[c];
        bv1[ni] = bias[c + 1];
    }

#pragma unroll
    for (int mi = 0; mi < 2; mi++) {
#pragma unroll
        for (int half = 0; half < 2; half++) {
            int r = bm + wm + mi * 16 + (lane >> 2) + half * 8;
            size_t rowoff = (size_t)r * N;
#pragma unroll
            for (int ni = 0; ni < 8; ni++) {
                int c = bn + wn + ni * 8 + 2 * (lane & 3);
                float v0 = acc[mi][ni][half * 2 + 0] + bv0[ni];
                float v1 = acc[mi][ni][half * 2 + 1] + bv1[ni];
                if (EPI == EPI_GELU) { v0 = gelu_tanh(v0); v1 = gelu_tanh(v1); }
                if (EPI == EPI_MLP2) {
                    float2 rr = *(const float2*)(res + rowoff + c);
                    v0 += rr.x; v1 += rr.y;
                }
                if (OUT_BF16) {
                    __nv_bfloat162 w = __floats2bfloat162_rn(v0, v1);
                    *(__nv_bfloat162*)((__nv_bfloat16*)Cout + rowoff + c) = w;
                } else {
                    float2 w = {v0, v1};
                    *(float2*)((float*)Cout + rowoff + c) = w;
                }
            }
        }
    }
}

// ---------------------------------------------------------------------------
// PROJ + residual + LN2 fused GEMM (unchanged).
// ---------------------------------------------------------------------------
#define PS_AS 40
#define PS_BS 264
#define PS_A_STG (64 * PS_AS)
#define PS_B_STG (32 * PS_BS)
#define PROJ_SMEM ((4 * PS_A_STG + 4 * PS_B_STG) * 2)   // 88064

__global__ void __launch_bounds__(256, 2) gemm_proj_ln(
    const __nv_bfloat16* __restrict__ A,
    const __nv_bfloat16* __restrict__ B,
    const float* __restrict__ bias,
    const float* __restrict__ xres,
    const float* __restrict__ gamma,
    const float* __restrict__ beta,
    float* __restrict__ x1,
    __nv_bfloat16* __restrict__ h2) {
    extern __shared__ __align__(16) __nv_bfloat16 smp[];
    __nv_bfloat16* Asm = smp;
    __nv_bfloat16* Bsm = smp + 4 * PS_A_STG;

    const int tid  = threadIdx.x;
    const int lane = tid & 31;
    const int wid  = tid >> 5;
    const int bm   = blockIdx.x * 64;
    const int wm   = (wid & 1) * 32;
    const int wn   = (wid >> 1) * 64;
    const int K = 256, N = 256;

    const __nv_bfloat16* Ab = A + (size_t)bm * K;

    float acc[2][8][4] = {};

    auto load_tile = [&](int k0, int stg) {
        __nv_bfloat16* as = Asm + stg * PS_A_STG;
        __nv_bfloat16* bs = Bsm + stg * PS_B_STG;
        {
            int row = tid >> 2, kc = (tid & 3) * 8;
            cpasync16(&as[row * PS_AS + kc], Ab + (size_t)row * K + k0 + kc);
        }
#pragma unroll
        for (int i = 0; i < 4; i++) {
            int c = tid + i * 256;
            int k = c >> 5, n = (c & 31) * 8;
            cpasync16(&bs[k * PS_BS + n], B + (size_t)(k0 + k) * N + n);
        }
        cp_commit();
    };

    const int nIter = 8;
    load_tile(0, 0);
    load_tile(32, 1);
    load_tile(64, 2);

    for (int i = 0; i < nIter; i++) {
        if      (i + 2 < nIter) cp_wait<2>();
        else if (i + 1 < nIter) cp_wait<1>();
        else                    cp_wait<0>();
        __syncthreads();
        if (i + 3 < nIter) load_tile((i + 3) * 32, (i + 3) & 3);

        const __nv_bfloat16* as = Asm + (i & 3) * PS_A_STG;
        const __nv_bfloat16* bs = Bsm + (i & 3) * PS_B_STG;
#pragma unroll
        for (int ks = 0; ks < 32; ks += 16) {
            uint32_t af[2][4];
#pragma unroll
            for (int mi = 0; mi < 2; mi++)
                ldsm4(af[mi], as + (wm + mi * 16 + (lane & 15)) * PS_AS
                                 + ks + (lane >> 4) * 8);
#pragma unroll
            for (int np = 0; np < 4; np++) {
                uint32_t bf[4];
                ldsm4t(bf, bs + (ks + (lane & 7) + ((lane >> 3) & 1) * 8) * PS_BS
                              + wn + np * 16 + (lane >> 4) * 8);
                mma_bf16(acc[0][np * 2 + 0], af[0], bf[0], bf[1]);
                mma_bf16(acc[1][np * 2 + 0], af[1], bf[0], bf[1]);
                mma_bf16(acc[0][np * 2 + 1], af[0], bf[2], bf[3]);
                mma_bf16(acc[1][np * 2 + 1], af[1], bf[2], bf[3]);
            }
        }
    }
    __syncthreads();

    // x1 = acc + bias + x, staged in smem
    float* x1s = (float*)smp;
    const int S = 264;

    float bv0[8], bv1[8];
#pragma unroll
    for (int ni = 0; ni < 8; ni++) {
        int c = wn + ni * 8 + 2 * (lane & 3);
        bv0[ni] = bias[c];
        bv1[ni] = bias[c + 1];
    }

#pragma unroll
    for (int mi = 0; mi < 2; mi++) {
#pragma unroll
        for (int half = 0; half < 2; half++) {
            int row  = wm + mi * 16 + (lane >> 2) + half * 8;
            int xrow = win_to_x_row(bm + row);
            size_t off = (size_t)xrow * 256;
#pragma unroll
            for (int ni = 0; ni < 8; ni++) {
                int c = wn + ni * 8 + 2 * (lane & 3);
                float v0 = acc[mi][ni][half * 2 + 0] + bv0[ni];
                float v1 = acc[mi][ni][half * 2 + 1] + bv1[ni];
                float2 rr = *(const float2*)(xres + off + c);
                v0 += rr.x; v1 += rr.y;
                float2 w = {v0, v1};
                *(float2*)(x1 + off + c)      = w;
                *(float2*)(&x1s[row * S + c]) = w;
            }
        }
    }
    __syncthreads();

    // in-block LN2
    float4 g0 = *(const float4*)(gamma + lane * 8);
    float4 g1 = *(const float4*)(gamma + lane * 8 + 4);
    float4 be0 = *(const float4*)(beta + lane * 8);
    float4 be1 = *(const float4*)(beta + lane * 8 + 4);

#pragma unroll
    for (int rr = 0; rr < 8; rr++) {
        int row = wid * 8 + rr;
        float4 u0 = *(const float4*)(&x1s[row * S + lane * 8]);
        float4 u1 = *(const float4*)(&x1s[row * S + lane * 8 + 4]);

        float s  = u0.x + u0.y + u0.z + u0.w + u1.x + u1.y + u1.z + u1.w;
        float ss = u0.x*u0.x + u0.y*u0.y + u0.z*u0.z + u0.w*u0.w
                 + u1.x*u1.x + u1.y*u1.y + u1.z*u1.z + u1.w*u1.w;
#pragma unroll
        for (int o = 16; o; o >>= 1) {
            s  += __shfl_xor_sync(0xffffffffu, s,  o);
            ss += __shfl_xor_sync(0xffffffffu, ss, o);
        }
        float mu  = s * (1.0f / 256.0f);
        float inv = rsqrtf(ss * (1.0f / 256.0f) - mu * mu + 1e-5f);

        float4 o0, o1;
        o0.x = (u0.x - mu) * inv * g0.x + be0.x;
        o0.y = (u0.y - mu) * inv * g0.y + be0.y;
        o0.z = (u0.z - mu) * inv * g0.z + be0.z;
        o0.w = (u0.w - mu) * inv * g0.w + be0.w;
        o1.x = (u1.x - mu) * inv * g1.x + be1.x;
        o1.y = (u1.y - mu) * inv * g1.y + be1.y;
        o1.z = (u1.z - mu) * inv * g1.z + be1.z;
        o1.w = (u1.w - mu) * inv * g1.w + be1.w;

        int xrow = win_to_x_row(bm + row);
        uint2 p0 = pack4_bf16(o0);
        uint2 p1 = pack4_bf16(o1);
        uint4 pk = make_uint4(p0.x, p0.y, p1.x, p1.y);
        *(uint4*)(h2 + (size_t)xrow * 256 + lane * 8) = pk;
    }
}

// ---------------------------------------------------------------------------
// Tensor-core windowed attention:
//  - K/V staged via cp.async (no LDG->reg->STS round trip)
//  - V fragments HOISTED (ldsm4t x8 once, instead of x32 across m-tiles)
//  - Q fragments direct from gmem; softmax via prescaled ex2 (R14)
// ---------------------------------------------------------------------------
#define ATS 40

__global__ void __launch_bounds__(64) attn_tc(const __nv_bfloat16* __restrict__ qkv,
                                              const float* __restrict__ bias_table,
                                              __nv_bfloat16* __restrict__ out) {
    __shared__ __align__(16) __nv_bfloat16 sK[2][64 * ATS];
    __shared__ __align__(16) __nv_bfloat16 sV[2][64 * ATS];
    __shared__ float sB[2][169];
    __shared__ int   sInfo[64];

    const int w     = blockIdx.x >> 2;
    const int wp    = threadIdx.x >> 5;
    const int lane  = threadIdx.x & 31;
    const int h     = (blockIdx.x & 3) * 2 + wp;
    const int wbase = w * 49;
    const int wi    = w & 63;

    // K/V rows 0..48 via cp.async (16B granules)
    for (int tsk = lane; tsk < 196; tsk += 32) {
        int row = tsk >> 2, seg = (tsk & 3) * 8;
        const __nv_bfloat16* base = qkv + (size_t)(wbase + row) * 768 + h * 32 + seg;
        int off = row * ATS + seg;
        cpasync16(&sK[wp][off], base + 256);
        cpasync16(&sV[wp][off], base + 512);
    }
    cp_commit();

    if (threadIdx.x < 64) {
        int j = threadIdx.x;
        int info;
        if (j < 49) {
            int rj = j / 7, cj = j - (j / 7) * 7;
            int gr = (wi >> 3) * 7 + rj;
            int gc = (wi & 7) * 7 + cj;
            int rh = (gr < 49) ? 0 : ((gr < 53) ? 1 : 2);
            int rc = (gc < 49) ? 0 : ((gc < 53) ? 1 : 2);
            int key = rj + 13 * cj;
            info = key | ((rh * 3 + rc) << 8) | (1 << 16);
        } else {
            info = 0 | (255 << 8);
        }
        sInfo[j] = info;
    }

    // bias prescaled by log2(e)
    for (int idx = lane; idx < 169; idx += 32)
        sB[wp][idx] = bias_table[idx * 8 + h] * LOG2E;

    cp_wait<0>();
    // zero pad rows 49..63 after async loads land
    for (int z = lane; z < 60; z += 32) {
        int row = 49 + (z >> 2), seg = (z & 3) * 8;
        int off = row * ATS + seg;
        uint4 zz = make_uint4(0, 0, 0, 0);
        *(uint4*)&sK[wp][off] = zz;
        *(uint4*)&sV[wp][off] = zz;
    }
    __syncthreads();

    const int q2 = 2 * (lane & 3);
    const int r = lane >> 2;
    const __nv_bfloat16* qb = qkv + (size_t)wbase * 768 + h * 32;

    // ---- V fragments hoisted: m-tile invariant, load once ----
    uint32_t vf[4][2][4];
#pragma unroll
    for (int ks = 0; ks < 4; ks++)
#pragma unroll
        for (int half = 0; half < 2; half++)
            ldsm4t(vf[ks][half],
                   &sV[wp][(ks * 16 + (lane & 7) + ((lane >> 3) & 1) * 8) * ATS
                           + half * 16 + (lane >> 4) * 8]);

#pragma unroll
    for (int mt = 0; mt < 4; mt++) {
        const int r0 = mt * 16 + r;
        const int r1 = r0 + 8;
        const bool v0 = (r0 < 49), v1 = (r1 < 49);
        uint32_t qf[2][4];
#pragma unroll
        for (int ks = 0; ks < 2; ks++) {
            const int cc = q2 + ks * 16;
            qf[ks][0] = v0 ? *(const uint32_t*)(qb + (size_t)r0 * 768 + cc)     : 0u;
            qf[ks][1] = v1 ? *(const uint32_t*)(qb + (size_t)r1 * 768 + cc)     : 0u;
            qf[ks][2] = v0 ? *(const uint32_t*)(qb + (size_t)r0 * 768 + cc + 8) : 0u;
            qf[ks][3] = v1 ? *(const uint32_t*)(qb + (size_t)r1 * 768 + cc + 8) : 0u;
        }

        float c[8][4] = {};
#pragma unroll
        for (int nt = 0; nt < 4; nt++) {
#pragma unroll
            for (int ks = 0; ks < 2; ks++) {
                uint32_t kf[4];
                ldsm4(kf, &sK[wp][(nt * 16 + (lane & 7) + ((lane >> 4) & 1) * 8) * ATS
                                  + ks * 16 + ((lane >> 3) & 1) * 8]);
                mma_bf16(c[2 * nt + 0], qf[ks], kf[0], kf[1]);
                mma_bf16(c[2 * nt + 1], qf[ks], kf[2], kf[3]);
            }
        }

        int infLo = sInfo[r0 < 64 ? r0 : 0], infHi = sInfo[r1 < 64 ? r1 : 0];
        int keyLo = (infLo & 255) + 84, regLo = (infLo >> 8) & 255;
        int keyHi = (infHi & 255) + 84, regHi = (infHi >> 8) & 255;

        float s0 = 0.0f, s1 = 0.0f, t0 = 0.0f, t1 = 0.0f;
#pragma unroll
        for (int u = 0; u < 8; u++) {
            int2 ii = *(const int2*)&sInfo[u * 8 + q2];
#pragma unroll
            for (int e = 0; e < 2; e++) {
                int inf = e ? ii.y : ii.x;
                float pLo, pHi;
                if (inf & 0x10000) {
                    int kj = inf & 255;
                    int rj = (inf >> 8) & 255;
                    float aLo = fmaf(c[u][e],     SCALE_Q_L2E, sB[wp][keyLo - kj]);
                    float aHi = fmaf(c[u][2 + e], SCALE_Q_L2E, sB[wp][keyHi - kj]);
                    if (rj != regLo) aLo -= MASK_L2E;
                    if (rj != regHi) aHi -= MASK_L2E;
                    pLo = ex2f(aLo);
                    pHi = ex2f(aHi);
                } else {
                    pLo = 0.0f; pHi = 0.0f;
                }
                c[u][e]     = pLo;
                c[u][2 + e] = pHi;
                if (e) { s1 += pLo; t1 += pHi; }
                else   { s0 += pLo; t0 += pHi; }
            }
        }
        float sumLo = s0 + s1;
        float sumHi = t0 + t1;
        sumLo += __shfl_xor_sync(0xffffffffu, sumLo, 1);
        sumLo += __shfl_xor_sync(0xffffffffu, sumLo, 2);
        sumHi += __shfl_xor_sync(0xffffffffu, sumHi, 1);
        sumHi += __shfl_xor_sync(0xffffffffu, sumHi, 2);
        float dLo = 1.0f / sumLo;
        float dHi = 1.0f / sumHi;

        uint32_t pa[4][4];
#pragma unroll
        for (int t = 0; t < 4; t++) {
            pa[t][0] = pack2_bf16(c[2 * t][0] * dLo,     c[2 * t][1] * dLo);
            pa[t][1] = pack2_bf16(c[2 * t][2] * dHi,     c[2 * t][3] * dHi);
            pa[t][2] = pack2_bf16(c[2 * t + 1][0] * dLo, c[2 * t + 1][1] * dLo);
            pa[t][3] = pack2_bf16(c[2 * t + 1][2] * dHi, c[2 * t + 1][3] * dHi);
        }

        float o[4][4] = {};
#pragma unroll
        for (int ks = 0; ks < 4; ks++) {
            mma_bf16(o[0], pa[ks], vf[ks][0][0], vf[ks][0][1]);
            mma_bf16(o[1], pa[ks], vf[ks][0][2], vf[ks][0][3]);
            mma_bf16(o[2], pa[ks], vf[ks][1][0], vf[ks][1][1]);
            mma_bf16(o[3], pa[ks], vf[ks][1][2], vf[ks][1][3]);
        }

        if (r0 < 49) {
            __nv_bfloat16* p = out + (size_t)(wbase + r0) * 256 + h * 32 + q2;
#pragma unroll
            for (int on = 0; on < 4; on++)
                *(uint32_t*)(p + on * 8) = pack2_bf16(o[on][0], o[on][1]);
        }
        if (r1 < 49) {
            __nv_bfloat16* p = out + (size_t)(wbase + r1) * 256 + h * 32 + q2;
#pragma unroll
            for (int on = 0; on < 4; on++)
                *(uint32_t*)(p + on * 8) = pack2_bf16(o[on][2], o[on][3]);
        }
    }
}

// ---------------------------------------------------------------------------
// Host launcher (graph-capturable: kernel launches only)
// ---------------------------------------------------------------------------
extern "C" void kernel_launch(void* const* d_in, const int* in_sizes, int n_in,
                              void* d_out, int out_size) {
    (void)in_sizes; (void)n_in; (void)out_size;

    const float* x          = (const float*)d_in[0];
    const float* n1g        = (const float*)d_in[1];
    const float* n1b        = (const float*)d_in[2];
    const float* qkv_w      = (const float*)d_in[3];
    const float* qkv_b      = (const float*)d_in[4];
    const float* proj_w     = (const float*)d_in[5];
    const float* proj_b     = (const float*)d_in[6];
    const float* bias_table = (const float*)d_in[7];
    const float* n2g        = (const float*)d_in[8];
    const float* n2b        = (const float*)d_in[9];
    const float* w1         = (const float*)d_in[10];
    const float* b1         = (const float*)d_in[11];
    const float* w2         = (const float*)d_in[12];
    const float* b2         = (const float*)d_in[13];
    float* out = (float*)d_out;

    __nv_bfloat16 *ywin, *qkvb, *attnb, *h2, *act, *wbf;
    float *x1;
    cudaGetSymbolAddress((void**)&ywin,  g_ywin);
    cudaGetSymbolAddress((void**)&qkvb,  g_qkv);
    cudaGetSymbolAddress((void**)&attnb, g_attn);
    cudaGetSymbolAddress((void**)&x1,    g_x1);
    cudaGetSymbolAddress((void**)&h2,    g_h2);
    cudaGetSymbolAddress((void**)&act,   g_act);
    cudaGetSymbolAddress((void**)&wbf,   g_wbf);

    cudaFuncSetAttribute(gemm_bf16<EPI_BIAS, true>,
                         cudaFuncAttributeMaxDynamicSharedMemorySize, GEMM_SMEM);
    cudaFuncSetAttribute(gemm_bf16<EPI_GELU, true>,
                         cudaFuncAttributeMaxDynamicSharedMemorySize, GEMM_SMEM);
    cudaFuncSetAttribute(gemm_bf16<EPI_MLP2, false>,
                         cudaFuncAttributeMaxDynamicSharedMemorySize, GEMM_SMEM);
    cudaFuncSetAttribute(gemm_proj_ln,
                         cudaFuncAttributeMaxDynamicSharedMemorySize, PROJ_SMEM);

    const int lnBlocks = NROWS / 8;

    // 0) weights -> bf16
    wconv_kernel<<<768, 1024>>>(qkv_w, proj_w, w1, w2, wbf);
    // 1) LN1 + cyclic shift + window partition -> bf16
    ln_kernel<<<lnBlocks, 256>>>(x, n1g, n1b, ywin);
    // 2) QKV: [100352,256] @ [256,768] -> bf16
    gemm_bf16<EPI_BIAS, true><<<dim3(6, 784), 256, GEMM_SMEM>>>(ywin, wbf + WOFF_QKV,
                                                                qkv_b, qkvb, nullptr, 768, 256);
    // 3) windowed attention (tensor cores) -> bf16
    attn_tc<<<NWIN * 4, 64>>>(qkvb, bias_table, attnb);
    // 4) proj + window-reverse + un-shift + residual + LN2 (fused) -> x1, h2
    gemm_proj_ln<<<1568, 256, PROJ_SMEM>>>(attnb, wbf + WOFF_PROJ, proj_b,
                                           x, n2g, n2b, x1, h2);
    // 5) MLP up + GELU: [100352,256] @ [256,1024] -> bf16
    gemm_bf16<EPI_GELU, true><<<dim3(8, 784), 256, GEMM_SMEM>>>(h2, wbf + WOFF_W1,
                                                                b1, act, nullptr, 1024, 256);
    // 6) MLP down + residual -> d_out (fp32): [100352,1024] @ [1024,256]
    gemm_bf16<EPI_MLP2, false><<<dim3(2, 784), 256, GEMM_SMEM>>>(act, wbf + WOFF_W2,
                                                                 b2, out, x1, 256, 1024);
}